// round 12
// baseline (speedup 1.0000x reference)
#include <cuda_runtime.h>
#include <cuda_bf16.h>
#include <cstdint>

#define SB 32
#define SS 128
#define HH 512
#define VV 32000
#define NSTEP 127
#define NCTA 148

__device__ float g_h[2][2][HH][SB];
__device__ float g_c[2][2][HH][SB];
__device__ __nv_bfloat16 g_hsp[2][2][2][SB][HH];  // [pp][layer][hi/lo][b][dim]
__device__ float g_k[SB][SS][HH];
__device__ float g_v[SB][SS][HH];
__device__ float g_q[SB][HH];
__device__ float g_attnT[HH][SB];
__device__ float g_attno[SB][HH];
__device__ unsigned long long g_amax[SB];
__device__ unsigned long long g_packed[SB];
__device__ __nv_bfloat16 g_wh[(size_t)VV * HH];
__device__ __nv_bfloat16 g_wl[(size_t)VV * HH];
__device__ __nv_bfloat16 g_embh[(size_t)VV * HH];
__device__ __nv_bfloat16 g_embl[(size_t)VV * HH];
__device__ __nv_bfloat16 g_lwh[2][4 * HH][2 * HH];
__device__ __nv_bfloat16 g_lwl[2][4 * HH][2 * HH];
__device__ unsigned g_arr[NCTA];

__device__ __forceinline__ float sigf(float x) { return 1.f / (1.f + expf(-x)); }
__device__ __forceinline__ unsigned long long amax_key(float v, int n) {
    unsigned u = __float_as_uint(v);
    u = (u & 0x80000000u) ? ~u : (u | 0x80000000u);
    return ((unsigned long long)u << 32) | (unsigned)(~(unsigned)n);
}

__device__ __forceinline__ unsigned ld_acq(const unsigned* p) {
    unsigned v;
    asm volatile("ld.acquire.gpu.global.b32 %0, [%1];" : "=r"(v) : "l"(p) : "memory");
    return v;
}
__device__ __forceinline__ void st_rel(unsigned* p, unsigned v) {
    asm volatile("st.release.gpu.global.b32 [%0], %1;" :: "l"(p), "r"(v) : "memory");
}

// single-hop all-poll grid barrier. Posting uses st.release (orders all prior
// writes); polling uses ld.acquire (orders all later reads). Strong ops only —
// the round-10 failure mode (weak cg spin-sync) is structurally excluded.
// Epochs are monotone, so a CTA racing ahead to epoch+1 cannot confuse pollers.
__device__ __forceinline__ void gridbar(unsigned ep) {
    __syncthreads();
    if (threadIdx.x == 0) st_rel(&g_arr[blockIdx.x], ep);
    if (threadIdx.x < NCTA) {
        while (ld_acq(&g_arr[threadIdx.x]) < ep) { }
    }
    __syncthreads();
}

__device__ __forceinline__ uint32_t smem_u32(const void* p) {
    uint32_t a;
    asm("{ .reg .u64 t; cvta.to.shared.u64 t, %1; cvt.u32.u64 %0, t; }" : "=r"(a) : "l"(p));
    return a;
}
__device__ __forceinline__ void ldsm_x4(uint32_t* r, uint32_t addr) {
    asm volatile("ldmatrix.sync.aligned.m8n8.x4.shared.b16 {%0,%1,%2,%3}, [%4];"
                 : "=r"(r[0]), "=r"(r[1]), "=r"(r[2]), "=r"(r[3]) : "r"(addr));
}
__device__ __forceinline__ void ldsm_x2(uint32_t* r, uint32_t addr) {
    asm volatile("ldmatrix.sync.aligned.m8n8.x2.shared.b16 {%0,%1}, [%2];"
                 : "=r"(r[0]), "=r"(r[1]) : "r"(addr));
}
__device__ __forceinline__ void mma_bf16(float* c, const uint32_t* a, const uint32_t* b) {
    asm volatile(
        "mma.sync.aligned.m16n8k16.row.col.f32.bf16.bf16.f32 "
        "{%0,%1,%2,%3}, {%4,%5,%6,%7}, {%8,%9}, {%0,%1,%2,%3};"
        : "+f"(c[0]), "+f"(c[1]), "+f"(c[2]), "+f"(c[3])
        : "r"(a[0]), "r"(a[1]), "r"(a[2]), "r"(a[3]), "r"(b[0]), "r"(b[1]));
}
__device__ __forceinline__ void cp16(uint32_t dst, const void* src) {
    asm volatile("cp.async.cg.shared.global [%0], [%1], 16;" :: "r"(dst), "l"(src));
}
__device__ __forceinline__ void cp_commit() { asm volatile("cp.async.commit_group;" ::: "memory"); }
template <int N>
__device__ __forceinline__ void cp_wait() { asm volatile("cp.async.wait_group %0;" :: "n"(N) : "memory"); }

#define ASTRIDE 520
#define L_ABYTES (64 * ASTRIDE * 2)              // 66560
#define L_BBUF   40960                            // 512 rows x 80B
#define SMEM_DYN (L_ABYTES + 2 * L_BBUF + 512)    // 148992

__global__ void init_kernel(const float* __restrict__ hidden, const float* __restrict__ cell,
                            const float* __restrict__ W_out, const float* __restrict__ emb,
                            const float* __restrict__ W_ih, const float* __restrict__ W_hh,
                            float* __restrict__ out) {
    const int idx = blockIdx.x * blockDim.x + threadIdx.x;
    const size_t stride = (size_t)gridDim.x * blockDim.x;
    if (idx < NCTA) g_arr[idx] = 0;
    if (idx < 2 * SB * HH) {
        int l = idx >> 14, b = (idx >> 9) & 31, h = idx & 511;
        float hv = hidden[idx];
        g_h[0][l][h][b] = hv;
        g_c[0][l][h][b] = cell[idx];
        __nv_bfloat16 hb = __float2bfloat16(hv);
        g_hsp[0][l][0][b][h] = hb;
        g_hsp[0][l][1][b][h] = __float2bfloat16(hv - __bfloat162float(hb));
    }
    if (idx < SB * VV) {
        int b = idx / VV, v = idx % VV;
        out[(size_t)b * SS * VV + v] = 0.f;
    }
    const size_t nw = (size_t)VV * HH;
    for (size_t i = idx; i < nw; i += stride) {
        float w = W_out[i];
        __nv_bfloat16 h = __float2bfloat16(w);
        g_wh[i] = h;
        g_wl[i] = __float2bfloat16(w - __bfloat162float(h));
        float e = emb[i];
        __nv_bfloat16 eh = __float2bfloat16(e);
        g_embh[i] = eh;
        g_embl[i] = __float2bfloat16(e - __bfloat162float(eh));
    }
    const size_t nlw = (size_t)2 * 4 * HH * 2 * HH;
    for (size_t i = idx; i < nlw; i += stride) {
        int l = (int)(i >> 21);
        int rem = (int)(i & ((1u << 21) - 1));
        int n = rem >> 10, k = rem & 1023;
        float w = (k < HH) ? W_ih[((size_t)l * 4 * HH + n) * HH + k]
                           : W_hh[((size_t)l * 4 * HH + n) * HH + (k - HH)];
        __nv_bfloat16 h = __float2bfloat16(w);
        g_lwh[l][n][k] = h;
        g_lwl[l][n][k] = __float2bfloat16(w - __bfloat162float(h));
    }
}

__global__ void kv_kernel(const float* __restrict__ hs, const float* __restrict__ W,
                          const float* __restrict__ bias, int which) {
    __shared__ float Ash[32][36];
    __shared__ float Wsh[32][132];
    float* dst = which ? &g_v[0][0][0] : &g_k[0][0][0];
    const int r0 = blockIdx.x * 32, n0 = blockIdx.y * 128;
    const int tid = threadIdx.x, lane = tid & 31, grp = tid >> 5;
    float acc[4][4] = {};
    for (int k0 = 0; k0 < HH; k0 += 32) {
        #pragma unroll
        for (int j = 0; j < 4; j++) {
            int m = grp + j * 8, r = r0 + m;
            Ash[lane][m] = hs[(size_t)(r & 127) * (SB * HH) + (r >> 7) * HH + k0 + lane];
        }
        #pragma unroll
        for (int j = 0; j < 16; j++) {
            int nn = grp + j * 8;
            Wsh[lane][nn] = W[(size_t)(n0 + nn) * HH + k0 + lane];
        }
        __syncthreads();
        #pragma unroll
        for (int k = 0; k < 32; k++) {
            float4 a4 = *(const float4*)&Ash[k][grp * 4];
            float4 w4 = *(const float4*)&Wsh[k][lane * 4];
            acc[0][0] += a4.x * w4.x; acc[0][1] += a4.x * w4.y; acc[0][2] += a4.x * w4.z; acc[0][3] += a4.x * w4.w;
            acc[1][0] += a4.y * w4.x; acc[1][1] += a4.y * w4.y; acc[1][2] += a4.y * w4.z; acc[1][3] += a4.y * w4.w;
            acc[2][0] += a4.z * w4.x; acc[2][1] += a4.z * w4.y; acc[2][2] += a4.z * w4.z; acc[2][3] += a4.z * w4.w;
            acc[3][0] += a4.w * w4.x; acc[3][1] += a4.w * w4.y; acc[3][2] += a4.w * w4.z; acc[3][3] += a4.w * w4.w;
        }
        __syncthreads();
    }
    const int nbase = n0 + lane * 4;
    float4 b4 = *(const float4*)&bias[nbase];
    #pragma unroll
    for (int i = 0; i < 4; i++) {
        int r = r0 + grp * 4 + i;
        float4 v;
        v.x = acc[i][0] + b4.x; v.y = acc[i][1] + b4.y;
        v.z = acc[i][2] + b4.z; v.w = acc[i][3] + b4.w;
        *(float4*)&dst[(size_t)r * HH + nbase] = v;
    }
}

// ---- LSTM via mma bf16 4-product split. 64 tiles x 8 np. (known-good) ----
__device__ void lstm_phase(int layer, int pin, int first, char* smem,
                           const float* __restrict__ b_ih, const float* __restrict__ b_hh) {
    const int tid = threadIdx.x, lane = tid & 31, w = tid >> 5;
    const int pout = pin ^ 1;
    const uint32_t abase[2] = {smem_u32(smem), smem_u32(smem + 17408)};
    const uint32_t wbase[2] = {smem_u32(smem + 34816), smem_u32(smem + 52224)};
    float (*Dsh)[33] = (float(*)[33])(smem + 69632);
    int* tok_s = (int*)(smem + 69632 + 4224);

    for (int tile = blockIdx.x; tile < 64; tile += gridDim.x) {
        const int np0 = tile * 8;
        if (tid < SB) {
            if (first) tok_s[tid] = 0;
            else tok_s[tid] = (int)(~(unsigned)(__ldcg(&g_packed[tid]) & 0xFFFFFFFFull));
        }
        __syncthreads();
        const int arow = tid >> 2;
        const int aseg = (tid & 3) * 64;

        auto issue = [&](int c, int buf) {
            const __nv_bfloat16* asrc;
            int s = arow >> 5, b = arow & 31, k0 = c * 128;
            if (k0 < HH) {
                if (layer == 0) asrc = (s ? g_embl : g_embh) + (size_t)tok_s[b] * HH + k0;
                else asrc = &g_hsp[pout][0][s][b][k0];
            } else asrc = &g_hsp[pin][layer][s][b][k0 - HH];
            uint32_t ad = abase[buf] + arow * 272 + aseg;
            const char* ap = (const char*)asrc + aseg;
            #pragma unroll
            for (int j = 0; j < 4; j++) cp16(ad + j * 16, ap + j * 16);
            int nl = arow & 31;
            int n = (nl >> 3) * HH + np0 + (nl & 7);
            const __nv_bfloat16* wsrc = (s ? &g_lwl[layer][n][0] : &g_lwh[layer][n][0]) + c * 128;
            uint32_t wd = wbase[buf] + arow * 272 + aseg;
            const char* wp = (const char*)wsrc + aseg;
            #pragma unroll
            for (int j = 0; j < 4; j++) cp16(wd + j * 16, wp + j * 16);
            cp_commit();
        };

        issue(0, 0);
        const int om = w & 1, nt = w >> 1;
        float acc[4] = {0.f, 0.f, 0.f, 0.f};
        for (int c = 0; c < 8; c++) {
            if (c < 7) { issue(c + 1, (c + 1) & 1); cp_wait<1>(); }
            else cp_wait<0>();
            __syncthreads();
            const uint32_t au = abase[c & 1], wu = wbase[c & 1];
            #pragma unroll
            for (int kt = 0; kt < 8; kt++) {
                uint32_t ah[4], al[4], wh[2], wl[2];
                int ar = om * 16 + (lane & 15);
                int kb = kt * 16 + ((lane >> 4) << 3);
                ldsm_x4(ah, au + ar * 272 + kb * 2);
                ldsm_x4(al, au + (ar + 32) * 272 + kb * 2);
                int wr = nt * 8 + (lane & 7);
                int kb2 = kt * 16 + ((lane & 8) ? 8 : 0);
                ldsm_x2(wh, wu + wr * 272 + kb2 * 2);
                ldsm_x2(wl, wu + (wr + 32) * 272 + kb2 * 2);
                mma_bf16(acc, ah, wh);
                mma_bf16(acc, ah, wl);
                mma_bf16(acc, al, wh);
                mma_bf16(acc, al, wl);
            }
            __syncthreads();
        }
        #pragma unroll
        for (int ci = 0; ci < 4; ci++) {
            int b = om * 16 + (lane >> 2) + ((ci >> 1) << 3);
            int nl = nt * 8 + (lane & 3) * 2 + (ci & 1);
            Dsh[nl][b] = acc[ci];
        }
        __syncthreads();
        {
            int i = tid >> 5, b = tid & 31, np = np0 + i;
            const size_t bo = (size_t)layer * 4 * HH;
            float s[4];
            #pragma unroll
            for (int g = 0; g < 4; g++)
                s[g] = Dsh[g * 8 + i][b] + b_ih[bo + g * HH + np] + b_hh[bo + g * HH + np];
            float cold = __ldcg(&g_c[pin][layer][np][b]);
            float cn = sigf(s[1]) * cold + sigf(s[0]) * tanhf(s[2]);
            float hn = sigf(s[3]) * tanhf(cn);
            __stcg(&g_c[pout][layer][np][b], cn);
            __stcg(&g_h[pout][layer][np][b], hn);
            __nv_bfloat16 hb = __float2bfloat16(hn);
            g_hsp[pout][layer][0][b][np] = hb;
            g_hsp[pout][layer][1][b][np] = __float2bfloat16(hn - __bfloat162float(hb));
        }
        __syncthreads();
    }
}

// ---- generic 512x512 projection: 128 tiles x 4 dims, intra-CTA K-split ----
__device__ void gemm512_phase(char* smem, const float* __restrict__ src,
                              const float* __restrict__ W, const float* __restrict__ bias,
                              float* __restrict__ dst) {
    float* xs = (float*)smem;                        // [512*32] floats
    float* ws = (float*)(smem + 65536);              // [4][516]
    float* part = (float*)(smem + 65536 + 8256);     // [8][32]
    const int tid = threadIdx.x, lane = tid & 31, w = tid >> 5;
    const uint32_t xu = smem_u32(xs), wu = smem_u32(ws);
    for (int tile = blockIdx.x; tile < 128; tile += gridDim.x) {
        const int d0 = tile * 4;
        #pragma unroll
        for (int j = 0; j < 16; j++) {
            int e = tid + j * 256;
            cp16(xu + e * 16, (const char*)src + e * 16);
        }
        #pragma unroll
        for (int j = 0; j < 2; j++) {
            int e = tid + j * 256;
            int row = e >> 7, seg = e & 127;
            cp16(wu + row * 2064 + seg * 16, W + (size_t)(d0 + row) * HH + seg * 4);
        }
        cp_commit();
        cp_wait<0>();
        __syncthreads();
        const int r = w >> 1, kh = w & 1;
        const float* wr = ws + r * 516 + kh * 256;
        const float* xp = xs + kh * 256 * 32;
        float acc = 0.f;
        #pragma unroll 8
        for (int k = 0; k < 256; k++) acc += xp[k * 32 + lane] * wr[k];
        part[w * 32 + lane] = acc;
        __syncthreads();
        if (tid < 128) {
            int rr = tid >> 5, b = tid & 31;
            float v = part[(rr * 2) * 32 + b] + part[(rr * 2 + 1) * 32 + b];
            __stcg(&dst[b * HH + d0 + rr], v + bias[d0 + rr]);
        }
        __syncthreads();
    }
}

// ---- attention ----
__device__ void attn_phase(char* smem) {
    float* qsm = (float*)smem;
    float* sc = qsm + 64;
    float* red = sc + 128;
    float (*pav)[64] = (float(*)[64])(red + 8);
    const int tid = threadIdx.x, lane = tid & 31, w = tid >> 5;
    for (int u = blockIdx.x; u < 256; u += gridDim.x) {
        const int b = u >> 3, hd = u & 7;
        if (hd == 0 && tid == 0) { __stcg(&g_amax[b], 0ull); __stcg(&g_packed[b], 0ull); }
        if (tid < 64) qsm[tid] = __ldcg(&g_q[b][hd * 64 + tid]);
        __syncthreads();
        if (tid < 128) {
            const float4* kr = (const float4*)&g_k[b][tid][hd * 64];
            const float4* q4 = (const float4*)qsm;
            float acc = 0.f;
            #pragma unroll
            for (int d4 = 0; d4 < 16; d4++) {
                float4 kv = kr[d4], qv = q4[d4];
                acc += qv.x * kv.x + qv.y * kv.y + qv.z * kv.z + qv.w * kv.w;
            }
            sc[tid] = acc * 0.125f;
        }
        __syncthreads();
        if (tid < 32) {
            float m = fmaxf(fmaxf(sc[tid], sc[tid + 32]), fmaxf(sc[tid + 64], sc[tid + 96]));
            #pragma unroll
            for (int off = 16; off; off >>= 1) m = fmaxf(m, __shfl_xor_sync(0xffffffffu, m, off));
            if (lane == 0) red[0] = m;
        }
        __syncthreads();
        float mm = red[0];
        if (tid < 128) {
            float e = expf(sc[tid] - mm);
            sc[tid] = e;
            float s = e;
            #pragma unroll
            for (int off = 16; off; off >>= 1) s += __shfl_xor_sync(0xffffffffu, s, off);
            if (lane == 0) red[1 + w] = s;
        }
        __syncthreads();
        float tot = red[1] + red[2] + red[3] + red[4];
        {
            int d = tid & 63, sg = tid >> 6;
            float acc = 0.f;
            #pragma unroll 8
            for (int s5 = 0; s5 < 32; s5++) {
                int s = sg * 32 + s5;
                acc += sc[s] * g_v[b][s][hd * 64 + d];
            }
            pav[sg][d] = acc;
        }
        __syncthreads();
        if (tid < 64)
            __stcg(&g_attnT[hd * 64 + tid][b],
                   (pav[0][tid] + pav[1][tid] + pav[2][tid] + pav[3][tid]) / tot);
        __syncthreads();
    }
}

// ---- logits: mma bf16-split, cp.async double-buffered B ----
__device__ void logits_phase(char* smem, const float* __restrict__ bout,
                             float* __restrict__ out, int t) {
    __nv_bfloat16* As = (__nv_bfloat16*)smem;
    const uint32_t bbase[2] = {smem_u32(smem + L_ABYTES), smem_u32(smem + L_ABYTES + L_BBUF)};
    unsigned long long* skey = (unsigned long long*)(smem + L_ABYTES + 2 * L_BBUF);
    const int tid = threadIdx.x, lane = tid & 31, w = tid >> 5;
    const uint32_t as_u = smem_u32(As);

    for (int tile = blockIdx.x; tile < 125; tile += gridDim.x) {
        const int n0 = tile * 256;
        if (tid < 32) skey[tid] = 0ull;

        auto issueB = [&](int c, int buf) {
            #pragma unroll
            for (int j = 0; j < 8; j++) {
                int e = j * 256 + tid;
                int rr = e >> 2, q = e & 3;
                const __nv_bfloat16* src = (rr & 256) ? g_wl : g_wh;
                cp16(bbase[buf] + rr * 80 + q * 16,
                     src + (size_t)(n0 + (rr & 255)) * HH + c * 32 + q * 8);
            }
            cp_commit();
        };
        issueB(0, 0);
        issueB(1, 1);

        for (int i2 = tid; i2 < 32 * HH; i2 += 256) {
            int m = i2 >> 9, k = i2 & 511;
            float x = __ldcg(&g_attno[m][k]);
            __nv_bfloat16 hb = __float2bfloat16(x);
            As[m * ASTRIDE + k] = hb;
            As[(32 + m) * ASTRIDE + k] = __float2bfloat16(x - __bfloat162float(hb));
        }

        float acc[2][4][4] = {};
        for (int kc = 0; kc < 16; kc++) {
            if (kc == 15) cp_wait<0>(); else cp_wait<1>();
            __syncthreads();
            const uint32_t bu = bbase[kc & 1];
            #pragma unroll
            for (int kk = 0; kk < 32; kk += 16) {
                const int ka = kc * 32 + kk;
                uint32_t ah[2][4], al[2][4], bh[4][2], bl[4][2];
                #pragma unroll
                for (int mt = 0; mt < 2; mt++) {
                    int r = mt * 16 + (lane & 15);
                    int k = ka + (((lane >> 4) & 1) << 3);
                    ldsm_x4(ah[mt], as_u + (r * ASTRIDE + k) * 2);
                    ldsm_x4(al[mt], as_u + ((32 + r) * ASTRIDE + k) * 2);
                }
                #pragma unroll
                for (int nt = 0; nt < 4; nt++) {
                    int nrow = w * 32 + nt * 8 + (lane & 7);
                    int k = kk + ((lane & 8) ? 8 : 0);
                    ldsm_x2(bh[nt], bu + nrow * 80 + k * 2);
                    ldsm_x2(bl[nt], bu + (256 + nrow) * 80 + k * 2);
                }
                #pragma unroll
                for (int mt = 0; mt < 2; mt++)
                    #pragma unroll
                    for (int nt = 0; nt < 4; nt++) {
                        mma_bf16(acc[mt][nt], ah[mt], bh[nt]);
                        mma_bf16(acc[mt][nt], ah[mt], bl[nt]);
                        mma_bf16(acc[mt][nt], al[mt], bh[nt]);
                    }
            }
            __syncthreads();
            if (kc + 2 < 16) issueB(kc + 2, kc & 1);
        }

        unsigned long long lkey[2][2] = {{0ull, 0ull}, {0ull, 0ull}};
        #pragma unroll
        for (int mt = 0; mt < 2; mt++)
            #pragma unroll
            for (int nt = 0; nt < 4; nt++) {
                int n = n0 + w * 32 + nt * 8 + (lane & 3) * 2;
                float2 bias = *(const float2*)&bout[n];
                #pragma unroll
                for (int h = 0; h < 2; h++) {
                    int b = mt * 16 + (lane >> 2) + h * 8;
                    float2 v;
                    v.x = acc[mt][nt][h * 2] + bias.x;
                    v.y = acc[mt][nt][h * 2 + 1] + bias.y;
                    *(float2*)&out[((size_t)b * SS + t + 1) * VV + n] = v;
                    unsigned long long k1 = amax_key(v.x, n);
                    unsigned long long k2 = amax_key(v.y, n + 1);
                    if (k2 > k1) k1 = k2;
                    if (k1 > lkey[mt][h]) lkey[mt][h] = k1;
                }
            }
        #pragma unroll
        for (int mt = 0; mt < 2; mt++)
            #pragma unroll
            for (int h = 0; h < 2; h++) {
                unsigned long long kk = lkey[mt][h];
                unsigned long long o = __shfl_xor_sync(0xffffffffu, kk, 1); if (o > kk) kk = o;
                o = __shfl_xor_sync(0xffffffffu, kk, 2); if (o > kk) kk = o;
                if ((lane & 3) == 0) atomicMax(&skey[mt * 16 + (lane >> 2) + h * 8], kk);
            }
        __syncthreads();
        if (tid < 32 && skey[tid]) atomicMax(&g_amax[tid], skey[tid]);
        __syncthreads();
    }
}

// ---- fix: 128 (b, quarter) units; fp32-exact argmax among candidates ----
__device__ void fix_phase(char* smem, const float* __restrict__ Wout,
                          const float* __restrict__ bout,
                          const float* __restrict__ out, int t) {
    float* ax = (float*)smem;
    const int tid = threadIdx.x, lane = tid & 31;
    for (int u = blockIdx.x; u < 128; u += gridDim.x) {
        const int b = u >> 2, qtr = u & 3;
        for (int d = tid; d < HH; d += 256) ax[d] = __ldcg(&g_attno[b][d]);
        __syncthreads();
        unsigned long long ak = __ldcg(&g_amax[b]);
        unsigned ue = (unsigned)(ak >> 32);
        unsigned uv = (ue & 0x80000000u) ? (ue & 0x7fffffffu) : ~ue;
        const float thr = __uint_as_float(uv) - 1e-2f;
        const float* row = out + ((size_t)b * SS + t + 1) * VV;
        unsigned long long best = 0ull;
        for (int n4 = qtr * 2000 + tid; n4 < (qtr + 1) * 2000; n4 += 256) {
            float4 v = __ldcg((const float4*)&row[n4 * 4]);
            float mv = fmaxf(fmaxf(v.x, v.y), fmaxf(v.z, v.w));
            if (mv >= thr) {
                float vv[4] = {v.x, v.y, v.z, v.w};
                #pragma unroll
                for (int j = 0; j < 4; j++) {
                    if (vv[j] >= thr) {
                        int n = n4 * 4 + j;
                        const float* wr = Wout + (size_t)n * HH;
                        float d = 0.f;
                        for (int k = 0; k < HH; k++) d += ax[k] * wr[k];
                        unsigned long long key = amax_key(d + bout[n], n);
                        if (key > best) best = key;
                    }
                }
            }
        }
        #pragma unroll
        for (int off = 16; off; off >>= 1) {
            unsigned long long o = __shfl_xor_sync(0xffffffffu, best, off);
            if (o > best) best = o;
        }
        __syncthreads();
        if (lane == 0 && best) atomicMax(&g_packed[b], best);
        __syncthreads();
    }
}

__global__ void __launch_bounds__(256, 1)
decoder_persist(const float* __restrict__ b_ih, const float* __restrict__ b_hh,
                const float* __restrict__ Wq, const float* __restrict__ bq,
                const float* __restrict__ Wo, const float* __restrict__ bo,
                const float* __restrict__ W_out, const float* __restrict__ b_out,
                float* __restrict__ out) {
    extern __shared__ char smem[];
    unsigned ep = 0;
    for (int t = 0; t < NSTEP; t++) {
        const int pin = t & 1, pout = pin ^ 1;
        lstm_phase(0, pin, t == 0, smem, b_ih, b_hh);
        gridbar(++ep);
        lstm_phase(1, pin, 0, smem, b_ih, b_hh);
        gridbar(++ep);
        gemm512_phase(smem, &g_h[pout][1][0][0], Wq, bq, &g_q[0][0]);
        gridbar(++ep);
        attn_phase(smem);
        gridbar(++ep);
        gemm512_phase(smem, &g_attnT[0][0], Wo, bo, &g_attno[0][0]);
        gridbar(++ep);
        logits_phase(smem, b_out, out, t);
        gridbar(++ep);
        fix_phase(smem, W_out, b_out, out, t);
        gridbar(++ep);
    }
}

extern "C" void kernel_launch(void* const* d_in, const int* in_sizes, int n_in,
                              void* d_out, int out_size) {
    const float* hs     = (const float*)d_in[0];
    const float* hidden = (const float*)d_in[1];
    const float* cell   = (const float*)d_in[2];
    const float* emb    = (const float*)d_in[3];
    const float* W_ih   = (const float*)d_in[4];
    const float* W_hh   = (const float*)d_in[5];
    const float* b_ih   = (const float*)d_in[6];
    const float* b_hh   = (const float*)d_in[7];
    const float* Wq     = (const float*)d_in[8];
    const float* bq     = (const float*)d_in[9];
    const float* Wk     = (const float*)d_in[10];
    const float* bk     = (const float*)d_in[11];
    const float* Wv     = (const float*)d_in[12];
    const float* bv     = (const float*)d_in[13];
    const float* Wo     = (const float*)d_in[14];
    const float* bo     = (const float*)d_in[15];
    const float* W_out  = (const float*)d_in[16];
    const float* b_out  = (const float*)d_in[17];
    float* out = (float*)d_out;

    cudaFuncSetAttribute(decoder_persist, cudaFuncAttributeMaxDynamicSharedMemorySize, SMEM_DYN);

    init_kernel<<<4000, 256>>>(hidden, cell, W_out, emb, W_ih, W_hh, out);

    dim3 kvg(128, 4);
    kv_kernel<<<kvg, 256>>>(hs, Wk, bk, 0);
    kv_kernel<<<kvg, 256>>>(hs, Wv, bv, 1);

    decoder_persist<<<NCTA, 256, SMEM_DYN>>>(b_ih, b_hh, Wq, bq, Wo, bo, W_out, b_out, out);
}

// round 13
// speedup vs baseline: 1.2446x; 1.2446x over previous
#include <cuda_runtime.h>
#include <cuda_bf16.h>
#include <cstdint>

#define SB 32
#define SS 128
#define HH 512
#define VV 32000
#define NSTEP 127
#define NCTA 148

__device__ float g_h[2][2][HH][SB];
__device__ float g_c[2][2][HH][SB];
__device__ __nv_bfloat16 g_hsp[2][2][2][SB][HH];  // [pp][layer][hi/lo][b][dim]
__device__ float g_k[SB][SS][HH];
__device__ float g_v[SB][SS][HH];
__device__ float g_q[SB][HH];
__device__ float g_attnT[HH][SB];
__device__ float g_attno[SB][HH];
__device__ unsigned long long g_amax[SB];
__device__ unsigned long long g_packed[SB];
__device__ __nv_bfloat16 g_wh[(size_t)VV * HH];
__device__ __nv_bfloat16 g_wl[(size_t)VV * HH];
__device__ __nv_bfloat16 g_embh[(size_t)VV * HH];
__device__ __nv_bfloat16 g_embl[(size_t)VV * HH];
__device__ __nv_bfloat16 g_lwh[2][4 * HH][2 * HH];
__device__ __nv_bfloat16 g_lwl[2][4 * HH][2 * HH];
__device__ unsigned g_arr[NCTA];   // arrival flags (atomic only)
__device__ unsigned g_rel[NCTA];   // release flags (atomic only)

__device__ __forceinline__ float sigf(float x) { return 1.f / (1.f + expf(-x)); }
__device__ __forceinline__ unsigned long long amax_key(float v, int n) {
    unsigned u = __float_as_uint(v);
    u = (u & 0x80000000u) ? ~u : (u | 0x80000000u);
    return ((unsigned long long)u << 32) | (unsigned)(~(unsigned)n);
}

// two-hop atomic flag-array grid barrier (round-11 proven-good)
__device__ __forceinline__ void gridbar(unsigned ep) {
    __syncthreads();
    if (blockIdx.x == 0) {
        if (threadIdx.x == 0) __threadfence();
        __syncthreads();
        if (threadIdx.x > 0 && threadIdx.x < NCTA) {
            while (atomicAdd(&g_arr[threadIdx.x], 0u) < ep) { }
        }
        __syncthreads();
        if (threadIdx.x == 0) __threadfence();
        __syncthreads();
        if (threadIdx.x < NCTA) atomicExch(&g_rel[threadIdx.x], ep);
    } else {
        if (threadIdx.x == 0) {
            __threadfence();
            atomicExch(&g_arr[blockIdx.x], ep);
            while (atomicAdd(&g_rel[blockIdx.x], 0u) < ep) { }
        }
    }
    __syncthreads();
}

__device__ __forceinline__ uint32_t smem_u32(const void* p) {
    uint32_t a;
    asm("{ .reg .u64 t; cvta.to.shared.u64 t, %1; cvt.u32.u64 %0, t; }" : "=r"(a) : "l"(p));
    return a;
}
__device__ __forceinline__ void ldsm_x4(uint32_t* r, uint32_t addr) {
    asm volatile("ldmatrix.sync.aligned.m8n8.x4.shared.b16 {%0,%1,%2,%3}, [%4];"
                 : "=r"(r[0]), "=r"(r[1]), "=r"(r[2]), "=r"(r[3]) : "r"(addr));
}
__device__ __forceinline__ void ldsm_x2(uint32_t* r, uint32_t addr) {
    asm volatile("ldmatrix.sync.aligned.m8n8.x2.shared.b16 {%0,%1}, [%2];"
                 : "=r"(r[0]), "=r"(r[1]) : "r"(addr));
}
__device__ __forceinline__ void mma_bf16(float* c, const uint32_t* a, const uint32_t* b) {
    asm volatile(
        "mma.sync.aligned.m16n8k16.row.col.f32.bf16.bf16.f32 "
        "{%0,%1,%2,%3}, {%4,%5,%6,%7}, {%8,%9}, {%0,%1,%2,%3};"
        : "+f"(c[0]), "+f"(c[1]), "+f"(c[2]), "+f"(c[3])
        : "r"(a[0]), "r"(a[1]), "r"(a[2]), "r"(a[3]), "r"(b[0]), "r"(b[1]));
}
__device__ __forceinline__ void cp16(uint32_t dst, const void* src) {
    asm volatile("cp.async.cg.shared.global [%0], [%1], 16;" :: "r"(dst), "l"(src));
}
__device__ __forceinline__ void cp_commit() { asm volatile("cp.async.commit_group;" ::: "memory"); }
template <int N>
__device__ __forceinline__ void cp_wait() { asm volatile("cp.async.wait_group %0;" :: "n"(N) : "memory"); }

#define ASTRIDE 520
#define L_ABYTES (64 * ASTRIDE * 2)              // 66560
#define L_BBUF   40960                            // 512 rows x 80B
#define SMEM_DYN (L_ABYTES + 2 * L_BBUF + 512)    // 148992

__global__ void init_kernel(const float* __restrict__ hidden, const float* __restrict__ cell,
                            const float* __restrict__ W_out, const float* __restrict__ emb,
                            const float* __restrict__ W_ih, const float* __restrict__ W_hh,
                            float* __restrict__ out) {
    const int idx = blockIdx.x * blockDim.x + threadIdx.x;
    const size_t stride = (size_t)gridDim.x * blockDim.x;
    if (idx < NCTA) { g_arr[idx] = 0; g_rel[idx] = 0; }
    if (idx < 2 * SB * HH) {
        int l = idx >> 14, b = (idx >> 9) & 31, h = idx & 511;
        float hv = hidden[idx];
        g_h[0][l][h][b] = hv;
        g_c[0][l][h][b] = cell[idx];
        __nv_bfloat16 hb = __float2bfloat16(hv);
        g_hsp[0][l][0][b][h] = hb;
        g_hsp[0][l][1][b][h] = __float2bfloat16(hv - __bfloat162float(hb));
    }
    if (idx < SB * VV) {
        int b = idx / VV, v = idx % VV;
        out[(size_t)b * SS * VV + v] = 0.f;
    }
    const size_t nw = (size_t)VV * HH;
    for (size_t i = idx; i < nw; i += stride) {
        float w = W_out[i];
        __nv_bfloat16 h = __float2bfloat16(w);
        g_wh[i] = h;
        g_wl[i] = __float2bfloat16(w - __bfloat162float(h));
        float e = emb[i];
        __nv_bfloat16 eh = __float2bfloat16(e);
        g_embh[i] = eh;
        g_embl[i] = __float2bfloat16(e - __bfloat162float(eh));
    }
    const size_t nlw = (size_t)2 * 4 * HH * 2 * HH;
    for (size_t i = idx; i < nlw; i += stride) {
        int l = (int)(i >> 21);
        int rem = (int)(i & ((1u << 21) - 1));
        int n = rem >> 10, k = rem & 1023;
        float w = (k < HH) ? W_ih[((size_t)l * 4 * HH + n) * HH + k]
                           : W_hh[((size_t)l * 4 * HH + n) * HH + (k - HH)];
        __nv_bfloat16 h = __float2bfloat16(w);
        g_lwh[l][n][k] = h;
        g_lwl[l][n][k] = __float2bfloat16(w - __bfloat162float(h));
    }
}

__global__ void kv_kernel(const float* __restrict__ hs, const float* __restrict__ W,
                          const float* __restrict__ bias, int which) {
    __shared__ float Ash[32][36];
    __shared__ float Wsh[32][132];
    float* dst = which ? &g_v[0][0][0] : &g_k[0][0][0];
    const int r0 = blockIdx.x * 32, n0 = blockIdx.y * 128;
    const int tid = threadIdx.x, lane = tid & 31, grp = tid >> 5;
    float acc[4][4] = {};
    for (int k0 = 0; k0 < HH; k0 += 32) {
        #pragma unroll
        for (int j = 0; j < 4; j++) {
            int m = grp + j * 8, r = r0 + m;
            Ash[lane][m] = hs[(size_t)(r & 127) * (SB * HH) + (r >> 7) * HH + k0 + lane];
        }
        #pragma unroll
        for (int j = 0; j < 16; j++) {
            int nn = grp + j * 8;
            Wsh[lane][nn] = W[(size_t)(n0 + nn) * HH + k0 + lane];
        }
        __syncthreads();
        #pragma unroll
        for (int k = 0; k < 32; k++) {
            float4 a4 = *(const float4*)&Ash[k][grp * 4];
            float4 w4 = *(const float4*)&Wsh[k][lane * 4];
            acc[0][0] += a4.x * w4.x; acc[0][1] += a4.x * w4.y; acc[0][2] += a4.x * w4.z; acc[0][3] += a4.x * w4.w;
            acc[1][0] += a4.y * w4.x; acc[1][1] += a4.y * w4.y; acc[1][2] += a4.y * w4.z; acc[1][3] += a4.y * w4.w;
            acc[2][0] += a4.z * w4.x; acc[2][1] += a4.z * w4.y; acc[2][2] += a4.z * w4.z; acc[2][3] += a4.z * w4.w;
            acc[3][0] += a4.w * w4.x; acc[3][1] += a4.w * w4.y; acc[3][2] += a4.w * w4.z; acc[3][3] += a4.w * w4.w;
        }
        __syncthreads();
    }
    const int nbase = n0 + lane * 4;
    float4 b4 = *(const float4*)&bias[nbase];
    #pragma unroll
    for (int i = 0; i < 4; i++) {
        int r = r0 + grp * 4 + i;
        float4 v;
        v.x = acc[i][0] + b4.x; v.y = acc[i][1] + b4.y;
        v.z = acc[i][2] + b4.z; v.w = acc[i][3] + b4.w;
        *(float4*)&dst[(size_t)r * HH + nbase] = v;
    }
}

// ---- LSTM via mma bf16 4-product split. 64 tiles x 8 np. 4-deep cp.async pipeline. ----
__device__ void lstm_phase(int layer, int pin, int first, char* smem,
                           const float* __restrict__ b_ih, const float* __restrict__ b_hh) {
    const int tid = threadIdx.x, lane = tid & 31, w = tid >> 5;
    const int pout = pin ^ 1;
    uint32_t abase[4], wbase[4];
    #pragma unroll
    for (int i = 0; i < 4; i++) {
        abase[i] = smem_u32(smem + i * 17408);
        wbase[i] = smem_u32(smem + 69632 + i * 17408);
    }
    float (*Dsh)[33] = (float(*)[33])(smem + 139264);
    int* tok_s = (int*)(smem + 141440);

    for (int tile = blockIdx.x; tile < 64; tile += gridDim.x) {
        const int np0 = tile * 8;
        if (tid < SB) {
            if (first) tok_s[tid] = 0;
            else tok_s[tid] = (int)(~(unsigned)(__ldcg(&g_packed[tid]) & 0xFFFFFFFFull));
        }
        __syncthreads();
        const int arow = tid >> 2;
        const int aseg = (tid & 3) * 64;

        auto issue = [&](int c, int buf) {
            const __nv_bfloat16* asrc;
            int s = arow >> 5, b = arow & 31, k0 = c * 128;
            if (k0 < HH) {
                if (layer == 0) asrc = (s ? g_embl : g_embh) + (size_t)tok_s[b] * HH + k0;
                else asrc = &g_hsp[pout][0][s][b][k0];
            } else asrc = &g_hsp[pin][layer][s][b][k0 - HH];
            uint32_t ad = abase[buf] + arow * 272 + aseg;
            const char* ap = (const char*)asrc + aseg;
            #pragma unroll
            for (int j = 0; j < 4; j++) cp16(ad + j * 16, ap + j * 16);
            int nl = arow & 31;
            int n = (nl >> 3) * HH + np0 + (nl & 7);
            const __nv_bfloat16* wsrc = (s ? &g_lwl[layer][n][0] : &g_lwh[layer][n][0]) + c * 128;
            uint32_t wd = wbase[buf] + arow * 272 + aseg;
            const char* wp = (const char*)wsrc + aseg;
            #pragma unroll
            for (int j = 0; j < 4; j++) cp16(wd + j * 16, wp + j * 16);
            cp_commit();
        };

        issue(0, 0); issue(1, 1); issue(2, 2);
        const int om = w & 1, nt = w >> 1;
        float acc[4] = {0.f, 0.f, 0.f, 0.f};
        for (int c = 0; c < 8; c++) {
            if (c + 3 < 8) issue(c + 3, (c + 3) & 3);
            if (c <= 4) cp_wait<3>();
            else if (c == 5) cp_wait<2>();
            else if (c == 6) cp_wait<1>();
            else cp_wait<0>();
            __syncthreads();
            const uint32_t au = abase[c & 3], wu = wbase[c & 3];
            #pragma unroll
            for (int kt = 0; kt < 8; kt++) {
                uint32_t ah[4], al[4], wh[2], wl[2];
                int ar = om * 16 + (lane & 15);
                int kb = kt * 16 + ((lane >> 4) << 3);
                ldsm_x4(ah, au + ar * 272 + kb * 2);
                ldsm_x4(al, au + (ar + 32) * 272 + kb * 2);
                int wr = nt * 8 + (lane & 7);
                int kb2 = kt * 16 + ((lane & 8) ? 8 : 0);
                ldsm_x2(wh, wu + wr * 272 + kb2 * 2);
                ldsm_x2(wl, wu + (wr + 32) * 272 + kb2 * 2);
                mma_bf16(acc, ah, wh);
                mma_bf16(acc, ah, wl);
                mma_bf16(acc, al, wh);
                mma_bf16(acc, al, wl);
            }
            __syncthreads();
        }
        #pragma unroll
        for (int ci = 0; ci < 4; ci++) {
            int b = om * 16 + (lane >> 2) + ((ci >> 1) << 3);
            int nl = nt * 8 + (lane & 3) * 2 + (ci & 1);
            Dsh[nl][b] = acc[ci];
        }
        __syncthreads();
        {
            int i = tid >> 5, b = tid & 31, np = np0 + i;
            const size_t bo = (size_t)layer * 4 * HH;
            float s[4];
            #pragma unroll
            for (int g = 0; g < 4; g++)
                s[g] = Dsh[g * 8 + i][b] + b_ih[bo + g * HH + np] + b_hh[bo + g * HH + np];
            float cold = __ldcg(&g_c[pin][layer][np][b]);
            float cn = sigf(s[1]) * cold + sigf(s[0]) * tanhf(s[2]);
            float hn = sigf(s[3]) * tanhf(cn);
            __stcg(&g_c[pout][layer][np][b], cn);
            __stcg(&g_h[pout][layer][np][b], hn);
            __nv_bfloat16 hb = __float2bfloat16(hn);
            g_hsp[pout][layer][0][b][np] = hb;
            g_hsp[pout][layer][1][b][np] = __float2bfloat16(hn - __bfloat162float(hb));
        }
        __syncthreads();
    }
}

// ---- generic 512x512 projection (round-11 64-tile version) ----
__device__ void gemm512_phase(char* smem, const float* __restrict__ src,
                              const float* __restrict__ W, const float* __restrict__ bias,
                              float* __restrict__ dst) {
    float* xs = (float*)smem;
    float* ws = (float*)(smem + 65536);
    const int tid = threadIdx.x;
    const uint32_t xu = smem_u32(xs), wu = smem_u32(ws);
    for (int tile = blockIdx.x; tile < 64; tile += gridDim.x) {
        const int d0 = tile * 8;
        #pragma unroll
        for (int j = 0; j < 16; j++) {
            int e = tid + j * 256;
            cp16(xu + e * 16, (const char*)src + e * 16);
        }
        #pragma unroll
        for (int j = 0; j < 4; j++) {
            int e = tid + j * 256;
            int row = e >> 7, seg = e & 127;
            cp16(wu + row * 2064 + seg * 16, W + (size_t)(d0 + row) * HH + seg * 4);
        }
        cp_commit();
        cp_wait<0>();
        __syncthreads();
        const int r = tid >> 5, b = tid & 31;
        const float* wr = ws + r * 516;
        float acc = 0.f;
        #pragma unroll 8
        for (int k = 0; k < HH; k++) acc += xs[k * 32 + b] * wr[k];
        __stcg(&dst[b * HH + d0 + r], acc + bias[d0 + r]);
        __syncthreads();
    }
}

// ---- attention: 2 half-block units per CTA (128 thr each); one pass over 256 units ----
__device__ void attn_phase(char* smem) {
    float (*qsm)[64]     = (float(*)[64])smem;                          // [2][64]
    float (*sc)[128]     = (float(*)[128])(smem + 512);                 // [2][128]
    float (*red)[8]      = (float(*)[8])(smem + 512 + 1024);            // [2][8]
    float (*pav)[2][64]  = (float(*)[2][64])(smem + 512 + 1024 + 64);   // [2][2][64]
    const int tid = threadIdx.x;
    const int h = tid >> 7, wt = tid & 127;
    const int lane = tid & 31, w4 = (tid >> 5) & 3;
    for (int ub = blockIdx.x * 2; ub < 256; ub += gridDim.x * 2) {
        const int u = ub + h;              // ub <= 254, so u < 256 always
        const int b = u >> 3, hd = u & 7;
        if (hd == 0 && wt == 0) { __stcg(&g_amax[b], 0ull); __stcg(&g_packed[b], 0ull); }
        if (wt < 64) qsm[h][wt] = __ldcg(&g_q[b][hd * 64 + wt]);
        __syncthreads();
        {
            const float4* kr = (const float4*)&g_k[b][wt][hd * 64];
            const float4* q4 = (const float4*)qsm[h];
            float acc = 0.f;
            #pragma unroll
            for (int d4 = 0; d4 < 16; d4++) {
                float4 kv = kr[d4], qv = q4[d4];
                acc += qv.x * kv.x + qv.y * kv.y + qv.z * kv.z + qv.w * kv.w;
            }
            sc[h][wt] = acc * 0.125f;
        }
        __syncthreads();
        if (wt < 32) {
            float m = fmaxf(fmaxf(sc[h][wt], sc[h][wt + 32]), fmaxf(sc[h][wt + 64], sc[h][wt + 96]));
            #pragma unroll
            for (int off = 16; off; off >>= 1) m = fmaxf(m, __shfl_xor_sync(0xffffffffu, m, off));
            if (lane == 0) red[h][0] = m;
        }
        __syncthreads();
        float mm = red[h][0];
        {
            float e = expf(sc[h][wt] - mm);
            sc[h][wt] = e;
            float s = e;
            #pragma unroll
            for (int off = 16; off; off >>= 1) s += __shfl_xor_sync(0xffffffffu, s, off);
            if (lane == 0) red[h][1 + w4] = s;
        }
        __syncthreads();
        float tot = red[h][1] + red[h][2] + red[h][3] + red[h][4];
        {
            int d = wt & 63, sg = wt >> 6;
            float acc = 0.f;
            #pragma unroll 8
            for (int s5 = 0; s5 < 64; s5++) {
                int s = sg * 64 + s5;
                acc += sc[h][s] * g_v[b][s][hd * 64 + d];
            }
            pav[h][sg][d] = acc;
        }
        __syncthreads();
        if (wt < 64)
            __stcg(&g_attnT[hd * 64 + wt][b], (pav[h][0][wt] + pav[h][1][wt]) / tot);
        __syncthreads();
    }
}

// ---- logits: mma bf16-split, cp.async double-buffered B (round-11 known-good) ----
__device__ void logits_phase(char* smem, const float* __restrict__ bout,
                             float* __restrict__ out, int t) {
    __nv_bfloat16* As = (__nv_bfloat16*)smem;
    const uint32_t bbase[2] = {smem_u32(smem + L_ABYTES), smem_u32(smem + L_ABYTES + L_BBUF)};
    unsigned long long* skey = (unsigned long long*)(smem + L_ABYTES + 2 * L_BBUF);
    const int tid = threadIdx.x, lane = tid & 31, w = tid >> 5;
    const uint32_t as_u = smem_u32(As);

    for (int tile = blockIdx.x; tile < 125; tile += gridDim.x) {
        const int n0 = tile * 256;
        if (tid < 32) skey[tid] = 0ull;

        auto issueB = [&](int c, int buf) {
            #pragma unroll
            for (int j = 0; j < 8; j++) {
                int e = j * 256 + tid;
                int rr = e >> 2, q = e & 3;
                const __nv_bfloat16* src = (rr & 256) ? g_wl : g_wh;
                cp16(bbase[buf] + rr * 80 + q * 16,
                     src + (size_t)(n0 + (rr & 255)) * HH + c * 32 + q * 8);
            }
            cp_commit();
        };
        issueB(0, 0);
        issueB(1, 1);

        for (int i2 = tid; i2 < 32 * HH; i2 += 256) {
            int m = i2 >> 9, k = i2 & 511;
            float x = __ldcg(&g_attno[m][k]);
            __nv_bfloat16 hb = __float2bfloat16(x);
            As[m * ASTRIDE + k] = hb;
            As[(32 + m) * ASTRIDE + k] = __float2bfloat16(x - __bfloat162float(hb));
        }

        float acc[2][4][4] = {};
        for (int kc = 0; kc < 16; kc++) {
            if (kc == 15) cp_wait<0>(); else cp_wait<1>();
            __syncthreads();
            const uint32_t bu = bbase[kc & 1];
            #pragma unroll
            for (int kk = 0; kk < 32; kk += 16) {
                const int ka = kc * 32 + kk;
                uint32_t ah[2][4], al[2][4], bh[4][2], bl[4][2];
                #pragma unroll
                for (int mt = 0; mt < 2; mt++) {
                    int r = mt * 16 + (lane & 15);
                    int k = ka + (((lane >> 4) & 1) << 3);
                    ldsm_x4(ah[mt], as_u + (r * ASTRIDE + k) * 2);
                    ldsm_x4(al[mt], as_u + ((32 + r) * ASTRIDE + k) * 2);
                }
                #pragma unroll
                for (int nt = 0; nt < 4; nt++) {
                    int nrow = w * 32 + nt * 8 + (lane & 7);
                    int k = kk + ((lane & 8) ? 8 : 0);
                    ldsm_x2(bh[nt], bu + nrow * 80 + k * 2);
                    ldsm_x2(bl[nt], bu + (256 + nrow) * 80 + k * 2);
                }
                #pragma unroll
                for (int mt = 0; mt < 2; mt++)
                    #pragma unroll
                    for (int nt = 0; nt < 4; nt++) {
                        mma_bf16(acc[mt][nt], ah[mt], bh[nt]);
                        mma_bf16(acc[mt][nt], ah[mt], bl[nt]);
                        mma_bf16(acc[mt][nt], al[mt], bh[nt]);
                    }
            }
            __syncthreads();
            if (kc + 2 < 16) issueB(kc + 2, kc & 1);
        }

        unsigned long long lkey[2][2] = {{0ull, 0ull}, {0ull, 0ull}};
        #pragma unroll
        for (int mt = 0; mt < 2; mt++)
            #pragma unroll
            for (int nt = 0; nt < 4; nt++) {
                int n = n0 + w * 32 + nt * 8 + (lane & 3) * 2;
                float2 bias = *(const float2*)&bout[n];
                #pragma unroll
                for (int h = 0; h < 2; h++) {
                    int b = mt * 16 + (lane >> 2) + h * 8;
                    float2 v;
                    v.x = acc[mt][nt][h * 2] + bias.x;
                    v.y = acc[mt][nt][h * 2 + 1] + bias.y;
                    *(float2*)&out[((size_t)b * SS + t + 1) * VV + n] = v;
                    unsigned long long k1 = amax_key(v.x, n);
                    unsigned long long k2 = amax_key(v.y, n + 1);
                    if (k2 > k1) k1 = k2;
                    if (k1 > lkey[mt][h]) lkey[mt][h] = k1;
                }
            }
        #pragma unroll
        for (int mt = 0; mt < 2; mt++)
            #pragma unroll
            for (int h = 0; h < 2; h++) {
                unsigned long long kk = lkey[mt][h];
                unsigned long long o = __shfl_xor_sync(0xffffffffu, kk, 1); if (o > kk) kk = o;
                o = __shfl_xor_sync(0xffffffffu, kk, 2); if (o > kk) kk = o;
                if ((lane & 3) == 0) atomicMax(&skey[mt * 16 + (lane >> 2) + h * 8], kk);
            }
        __syncthreads();
        if (tid < 32 && skey[tid]) atomicMax(&g_amax[tid], skey[tid]);
        __syncthreads();
    }
}

// ---- fix: 128 (b, quarter) units; fp32-exact argmax among candidates ----
__device__ void fix_phase(char* smem, const float* __restrict__ Wout,
                          const float* __restrict__ bout,
                          const float* __restrict__ out, int t) {
    float* ax = (float*)smem;
    const int tid = threadIdx.x, lane = tid & 31;
    for (int u = blockIdx.x; u < 128; u += gridDim.x) {
        const int b = u >> 2, qtr = u & 3;
        for (int d = tid; d < HH; d += 256) ax[d] = __ldcg(&g_attno[b][d]);
        __syncthreads();
        unsigned long long ak = __ldcg(&g_amax[b]);
        unsigned ue = (unsigned)(ak >> 32);
        unsigned uv = (ue & 0x80000000u) ? (ue & 0x7fffffffu) : ~ue;
        const float thr = __uint_as_float(uv) - 1e-2f;
        const float* row = out + ((size_t)b * SS + t + 1) * VV;
        unsigned long long best = 0ull;
        for (int n4 = qtr * 2000 + tid; n4 < (qtr + 1) * 2000; n4 += 256) {
            float4 v = __ldcg((const float4*)&row[n4 * 4]);
            float mv = fmaxf(fmaxf(v.x, v.y), fmaxf(v.z, v.w));
            if (mv >= thr) {
                float vv[4] = {v.x, v.y, v.z, v.w};
                #pragma unroll
                for (int j = 0; j < 4; j++) {
                    if (vv[j] >= thr) {
                        int n = n4 * 4 + j;
                        const float* wr = Wout + (size_t)n * HH;
                        float d = 0.f;
                        for (int k = 0; k < HH; k++) d += ax[k] * wr[k];
                        unsigned long long key = amax_key(d + bout[n], n);
                        if (key > best) best = key;
                    }
                }
            }
        }
        #pragma unroll
        for (int off = 16; off; off >>= 1) {
            unsigned long long o = __shfl_xor_sync(0xffffffffu, best, off);
            if (o > best) best = o;
        }
        __syncthreads();
        if (lane == 0 && best) atomicMax(&g_packed[b], best);
        __syncthreads();
    }
}

__global__ void __launch_bounds__(256, 1)
decoder_persist(const float* __restrict__ b_ih, const float* __restrict__ b_hh,
                const float* __restrict__ Wq, const float* __restrict__ bq,
                const float* __restrict__ Wo, const float* __restrict__ bo,
                const float* __restrict__ W_out, const float* __restrict__ b_out,
                float* __restrict__ out) {
    extern __shared__ char smem[];
    unsigned ep = 0;
    for (int t = 0; t < NSTEP; t++) {
        const int pin = t & 1, pout = pin ^ 1;
        lstm_phase(0, pin, t == 0, smem, b_ih, b_hh);
        gridbar(++ep);
        lstm_phase(1, pin, 0, smem, b_ih, b_hh);
        gridbar(++ep);
        gemm512_phase(smem, &g_h[pout][1][0][0], Wq, bq, &g_q[0][0]);
        gridbar(++ep);
        attn_phase(smem);
        gridbar(++ep);
        gemm512_phase(smem, &g_attnT[0][0], Wo, bo, &g_attno[0][0]);
        gridbar(++ep);
        logits_phase(smem, b_out, out, t);
        gridbar(++ep);
        fix_phase(smem, W_out, b_out, out, t);
        gridbar(++ep);
    }
}

extern "C" void kernel_launch(void* const* d_in, const int* in_sizes, int n_in,
                              void* d_out, int out_size) {
    const float* hs     = (const float*)d_in[0];
    const float* hidden = (const float*)d_in[1];
    const float* cell   = (const float*)d_in[2];
    const float* emb    = (const float*)d_in[3];
    const float* W_ih   = (const float*)d_in[4];
    const float* W_hh   = (const float*)d_in[5];
    const float* b_ih   = (const float*)d_in[6];
    const float* b_hh   = (const float*)d_in[7];
    const float* Wq     = (const float*)d_in[8];
    const float* bq     = (const float*)d_in[9];
    const float* Wk     = (const float*)d_in[10];
    const float* bk     = (const float*)d_in[11];
    const float* Wv     = (const float*)d_in[12];
    const float* bv     = (const float*)d_in[13];
    const float* Wo     = (const float*)d_in[14];
    const float* bo     = (const float*)d_in[15];
    const float* W_out  = (const float*)d_in[16];
    const float* b_out  = (const float*)d_in[17];
    float* out = (float*)d_out;

    cudaFuncSetAttribute(decoder_persist, cudaFuncAttributeMaxDynamicSharedMemorySize, SMEM_DYN);

    init_kernel<<<4000, 256>>>(hidden, cell, W_out, emb, W_ih, W_hh, out);

    dim3 kvg(128, 4);
    kv_kernel<<<kvg, 256>>>(hs, Wk, bk, 0);
    kv_kernel<<<kvg, 256>>>(hs, Wv, bv, 1);

    decoder_persist<<<NCTA, 256, SMEM_DYN>>>(b_ih, b_hh, Wq, bq, Wo, bo, W_out, b_out, out);
}

// round 14
// speedup vs baseline: 1.2865x; 1.0337x over previous
#include <cuda_runtime.h>
#include <cuda_bf16.h>
#include <cstdint>

#define SB 32
#define SS 128
#define HH 512
#define VV 32000
#define NSTEP 127
#define NCTA 148

__device__ float g_h[2][2][HH][SB];
__device__ float g_c[2][2][HH][SB];
__device__ __nv_bfloat16 g_hsp[2][2][2][SB][HH];  // [pp][layer][hi/lo][b][dim]
__device__ float g_k[SB][SS][HH];
__device__ float g_v[SB][SS][HH];
__device__ float g_q[SB][HH];
__device__ float g_attnT[HH][SB];
__device__ float g_attno[SB][HH];
__device__ unsigned long long g_amax[SB];
__device__ unsigned long long g_packed[SB];
__device__ __nv_bfloat16 g_wh[(size_t)VV * HH];
__device__ __nv_bfloat16 g_wl[(size_t)VV * HH];
__device__ __nv_bfloat16 g_embh[(size_t)VV * HH];
__device__ __nv_bfloat16 g_embl[(size_t)VV * HH];
__device__ __nv_bfloat16 g_lwh[2][4 * HH][2 * HH];
__device__ __nv_bfloat16 g_lwl[2][4 * HH][2 * HH];
__device__ unsigned g_arr[NCTA];
__device__ unsigned g_rel[NCTA];

__device__ __forceinline__ float sigf(float x) { return 1.f / (1.f + expf(-x)); }
__device__ __forceinline__ unsigned long long amax_key(float v, int n) {
    unsigned u = __float_as_uint(v);
    u = (u & 0x80000000u) ? ~u : (u | 0x80000000u);
    return ((unsigned long long)u << 32) | (unsigned)(~(unsigned)n);
}

// two-hop atomic flag-array grid barrier (proven-good)
__device__ __forceinline__ void gridbar(unsigned ep) {
    __syncthreads();
    if (blockIdx.x == 0) {
        if (threadIdx.x == 0) __threadfence();
        __syncthreads();
        if (threadIdx.x > 0 && threadIdx.x < NCTA) {
            while (atomicAdd(&g_arr[threadIdx.x], 0u) < ep) { }
        }
        __syncthreads();
        if (threadIdx.x == 0) __threadfence();
        __syncthreads();
        if (threadIdx.x < NCTA) atomicExch(&g_rel[threadIdx.x], ep);
    } else {
        if (threadIdx.x == 0) {
            __threadfence();
            atomicExch(&g_arr[blockIdx.x], ep);
            while (atomicAdd(&g_rel[blockIdx.x], 0u) < ep) { }
        }
    }
    __syncthreads();
}

__device__ __forceinline__ uint32_t smem_u32(const void* p) {
    uint32_t a;
    asm("{ .reg .u64 t; cvta.to.shared.u64 t, %1; cvt.u32.u64 %0, t; }" : "=r"(a) : "l"(p));
    return a;
}
__device__ __forceinline__ void ldsm_x4(uint32_t* r, uint32_t addr) {
    asm volatile("ldmatrix.sync.aligned.m8n8.x4.shared.b16 {%0,%1,%2,%3}, [%4];"
                 : "=r"(r[0]), "=r"(r[1]), "=r"(r[2]), "=r"(r[3]) : "r"(addr));
}
__device__ __forceinline__ void ldsm_x2(uint32_t* r, uint32_t addr) {
    asm volatile("ldmatrix.sync.aligned.m8n8.x2.shared.b16 {%0,%1}, [%2];"
                 : "=r"(r[0]), "=r"(r[1]) : "r"(addr));
}
__device__ __forceinline__ void mma_bf16(float* c, const uint32_t* a, const uint32_t* b) {
    asm volatile(
        "mma.sync.aligned.m16n8k16.row.col.f32.bf16.bf16.f32 "
        "{%0,%1,%2,%3}, {%4,%5,%6,%7}, {%8,%9}, {%0,%1,%2,%3};"
        : "+f"(c[0]), "+f"(c[1]), "+f"(c[2]), "+f"(c[3])
        : "r"(a[0]), "r"(a[1]), "r"(a[2]), "r"(a[3]), "r"(b[0]), "r"(b[1]));
}
__device__ __forceinline__ void cp16(uint32_t dst, const void* src) {
    asm volatile("cp.async.cg.shared.global [%0], [%1], 16;" :: "r"(dst), "l"(src));
}
__device__ __forceinline__ void cp_commit() { asm volatile("cp.async.commit_group;" ::: "memory"); }
template <int N>
__device__ __forceinline__ void cp_wait() { asm volatile("cp.async.wait_group %0;" :: "n"(N) : "memory"); }

#define ASTRIDE 520
#define L_ABYTES (64 * ASTRIDE * 2)              // 66560
#define L_BBUF   40960                            // 512 rows x 80B
#define SMEM_DYN (L_ABYTES + 2 * L_BBUF + 512)    // 148992

__global__ void init_kernel(const float* __restrict__ hidden, const float* __restrict__ cell,
                            const float* __restrict__ W_out, const float* __restrict__ emb,
                            const float* __restrict__ W_ih, const float* __restrict__ W_hh,
                            float* __restrict__ out) {
    const int idx = blockIdx.x * blockDim.x + threadIdx.x;
    const size_t stride = (size_t)gridDim.x * blockDim.x;
    if (idx < NCTA) { g_arr[idx] = 0; g_rel[idx] = 0; }
    if (idx < 2 * SB * HH) {
        int l = idx >> 14, b = (idx >> 9) & 31, h = idx & 511;
        float hv = hidden[idx];
        g_h[0][l][h][b] = hv;
        g_c[0][l][h][b] = cell[idx];
        __nv_bfloat16 hb = __float2bfloat16(hv);
        g_hsp[0][l][0][b][h] = hb;
        g_hsp[0][l][1][b][h] = __float2bfloat16(hv - __bfloat162float(hb));
    }
    if (idx < SB * VV) {
        int b = idx / VV, v = idx % VV;
        out[(size_t)b * SS * VV + v] = 0.f;
    }
    const size_t nw = (size_t)VV * HH;
    for (size_t i = idx; i < nw; i += stride) {
        float w = W_out[i];
        __nv_bfloat16 h = __float2bfloat16(w);
        g_wh[i] = h;
        g_wl[i] = __float2bfloat16(w - __bfloat162float(h));
        float e = emb[i];
        __nv_bfloat16 eh = __float2bfloat16(e);
        g_embh[i] = eh;
        g_embl[i] = __float2bfloat16(e - __bfloat162float(eh));
    }
    const size_t nlw = (size_t)2 * 4 * HH * 2 * HH;
    for (size_t i = idx; i < nlw; i += stride) {
        int l = (int)(i >> 21);
        int rem = (int)(i & ((1u << 21) - 1));
        int n = rem >> 10, k = rem & 1023;
        float w = (k < HH) ? W_ih[((size_t)l * 4 * HH + n) * HH + k]
                           : W_hh[((size_t)l * 4 * HH + n) * HH + (k - HH)];
        __nv_bfloat16 h = __float2bfloat16(w);
        g_lwh[l][n][k] = h;
        g_lwl[l][n][k] = __float2bfloat16(w - __bfloat162float(h));
    }
}

__global__ void kv_kernel(const float* __restrict__ hs, const float* __restrict__ W,
                          const float* __restrict__ bias, int which) {
    __shared__ float Ash[32][36];
    __shared__ float Wsh[32][132];
    float* dst = which ? &g_v[0][0][0] : &g_k[0][0][0];
    const int r0 = blockIdx.x * 32, n0 = blockIdx.y * 128;
    const int tid = threadIdx.x, lane = tid & 31, grp = tid >> 5;
    float acc[4][4] = {};
    for (int k0 = 0; k0 < HH; k0 += 32) {
        #pragma unroll
        for (int j = 0; j < 4; j++) {
            int m = grp + j * 8, r = r0 + m;
            Ash[lane][m] = hs[(size_t)(r & 127) * (SB * HH) + (r >> 7) * HH + k0 + lane];
        }
        #pragma unroll
        for (int j = 0; j < 16; j++) {
            int nn = grp + j * 8;
            Wsh[lane][nn] = W[(size_t)(n0 + nn) * HH + k0 + lane];
        }
        __syncthreads();
        #pragma unroll
        for (int k = 0; k < 32; k++) {
            float4 a4 = *(const float4*)&Ash[k][grp * 4];
            float4 w4 = *(const float4*)&Wsh[k][lane * 4];
            acc[0][0] += a4.x * w4.x; acc[0][1] += a4.x * w4.y; acc[0][2] += a4.x * w4.z; acc[0][3] += a4.x * w4.w;
            acc[1][0] += a4.y * w4.x; acc[1][1] += a4.y * w4.y; acc[1][2] += a4.y * w4.z; acc[1][3] += a4.y * w4.w;
            acc[2][0] += a4.z * w4.x; acc[2][1] += a4.z * w4.y; acc[2][2] += a4.z * w4.z; acc[2][3] += a4.z * w4.w;
            acc[3][0] += a4.w * w4.x; acc[3][1] += a4.w * w4.y; acc[3][2] += a4.w * w4.z; acc[3][3] += a4.w * w4.w;
        }
        __syncthreads();
    }
    const int nbase = n0 + lane * 4;
    float4 b4 = *(const float4*)&bias[nbase];
    #pragma unroll
    for (int i = 0; i < 4; i++) {
        int r = r0 + grp * 4 + i;
        float4 v;
        v.x = acc[i][0] + b4.x; v.y = acc[i][1] + b4.y;
        v.z = acc[i][2] + b4.z; v.w = acc[i][3] + b4.w;
        *(float4*)&dst[(size_t)r * HH + nbase] = v;
    }
}

// ---- LSTM: 128 tiles x np=4; warps m2 x n2 x k2; bf16 4-product; 4-deep cp.async ----
__device__ void lstm_phase(int layer, int pin, int first, char* smem,
                           const float* __restrict__ b_ih, const float* __restrict__ b_hh) {
    const int tid = threadIdx.x, lane = tid & 31, w = tid >> 5;
    const int pout = pin ^ 1;
    uint32_t abase[4], wbase[4];
    #pragma unroll
    for (int i = 0; i < 4; i++) {
        abase[i] = smem_u32(smem + i * 17408);                 // A: 64 rows x 272B
        wbase[i] = smem_u32(smem + 69632 + i * 8704);          // W: 32 rows x 272B
    }
    float (*Dsh)[16][33] = (float(*)[16][33])(smem + 104448);  // [2][16][33]
    int* tok_s = (int*)(smem + 104448 + 4224);

    for (int tile = blockIdx.x; tile < 128; tile += gridDim.x) {
        const int np0 = tile * 4;
        if (tid < SB) {
            if (first) tok_s[tid] = 0;
            else tok_s[tid] = (int)(~(unsigned)(__ldcg(&g_packed[tid]) & 0xFFFFFFFFull));
        }
        __syncthreads();
        const int arow = tid >> 2, aseg = (tid & 3) * 64;
        const int wrow = tid >> 3, wseg = (tid & 7) * 32;

        auto issue = [&](int c, int buf) {
            const __nv_bfloat16* asrc;
            int s = arow >> 5, b = arow & 31, k0 = c * 128;
            if (k0 < HH) {
                if (layer == 0) asrc = (s ? g_embl : g_embh) + (size_t)tok_s[b] * HH + k0;
                else asrc = &g_hsp[pout][0][s][b][k0];
            } else asrc = &g_hsp[pin][layer][s][b][k0 - HH];
            uint32_t ad = abase[buf] + arow * 272 + aseg;
            const char* ap = (const char*)asrc + aseg;
            #pragma unroll
            for (int j = 0; j < 4; j++) cp16(ad + j * 16, ap + j * 16);
            int ws = wrow >> 4, nl = wrow & 15;
            int n = (nl >> 2) * HH + np0 + (nl & 3);
            const __nv_bfloat16* wsrc = (ws ? &g_lwl[layer][n][0] : &g_lwh[layer][n][0]) + c * 128;
            uint32_t wd = wbase[buf] + wrow * 272 + wseg;
            const char* wp = (const char*)wsrc + wseg;
            cp16(wd, wp);
            cp16(wd + 16, wp + 16);
            cp_commit();
        };

        issue(0, 0); issue(1, 1); issue(2, 2);
        const int om = w & 1, nt = (w >> 1) & 1, kh = w >> 2;
        float acc[4] = {0.f, 0.f, 0.f, 0.f};
        for (int c = 0; c < 8; c++) {
            if (c + 3 < 8) issue(c + 3, (c + 3) & 3);
            if (c <= 4) cp_wait<3>();
            else if (c == 5) cp_wait<2>();
            else if (c == 6) cp_wait<1>();
            else cp_wait<0>();
            __syncthreads();
            const uint32_t au = abase[c & 3], wu = wbase[c & 3];
            #pragma unroll
            for (int kj = 0; kj < 4; kj++) {
                int kt = kh * 4 + kj;
                uint32_t ah[4], al[4], wh[2], wl[2];
                int ar = om * 16 + (lane & 15);
                int kb = kt * 16 + ((lane >> 4) << 3);
                ldsm_x4(ah, au + ar * 272 + kb * 2);
                ldsm_x4(al, au + (ar + 32) * 272 + kb * 2);
                int wr = nt * 8 + (lane & 7);
                int kb2 = kt * 16 + ((lane & 8) ? 8 : 0);
                ldsm_x2(wh, wu + wr * 272 + kb2 * 2);
                ldsm_x2(wl, wu + (wr + 16) * 272 + kb2 * 2);
                mma_bf16(acc, ah, wh);
                mma_bf16(acc, ah, wl);
                mma_bf16(acc, al, wh);
                mma_bf16(acc, al, wl);
            }
            __syncthreads();
        }
        #pragma unroll
        for (int ci = 0; ci < 4; ci++) {
            int b = om * 16 + (lane >> 2) + ((ci >> 1) << 3);
            int nl = nt * 8 + (lane & 3) * 2 + (ci & 1);
            Dsh[kh][nl][b] = acc[ci];
        }
        __syncthreads();
        if (tid < 128) {
            int i = tid >> 5, b = tid & 31, np = np0 + i;
            const size_t bo = (size_t)layer * 4 * HH;
            float s[4];
            #pragma unroll
            for (int g = 0; g < 4; g++)
                s[g] = Dsh[0][g * 4 + i][b] + Dsh[1][g * 4 + i][b]
                     + b_ih[bo + g * HH + np] + b_hh[bo + g * HH + np];
            float cold = __ldcg(&g_c[pin][layer][np][b]);
            float cn = sigf(s[1]) * cold + sigf(s[0]) * tanhf(s[2]);
            float hn = sigf(s[3]) * tanhf(cn);
            __stcg(&g_c[pout][layer][np][b], cn);
            __stcg(&g_h[pout][layer][np][b], hn);
            __nv_bfloat16 hb = __float2bfloat16(hn);
            g_hsp[pout][layer][0][b][np] = hb;
            g_hsp[pout][layer][1][b][np] = __float2bfloat16(hn - __bfloat162float(hb));
        }
        __syncthreads();
    }
}

// ---- generic 512x512 projection (64-tile proven version) ----
__device__ void gemm512_phase(char* smem, const float* __restrict__ src,
                              const float* __restrict__ W, const float* __restrict__ bias,
                              float* __restrict__ dst) {
    float* xs = (float*)smem;
    float* ws = (float*)(smem + 65536);
    const int tid = threadIdx.x;
    const uint32_t xu = smem_u32(xs), wu = smem_u32(ws);
    for (int tile = blockIdx.x; tile < 64; tile += gridDim.x) {
        const int d0 = tile * 8;
        #pragma unroll
        for (int j = 0; j < 16; j++) {
            int e = tid + j * 256;
            cp16(xu + e * 16, (const char*)src + e * 16);
        }
        #pragma unroll
        for (int j = 0; j < 4; j++) {
            int e = tid + j * 256;
            int row = e >> 7, seg = e & 127;
            cp16(wu + row * 2064 + seg * 16, W + (size_t)(d0 + row) * HH + seg * 4);
        }
        cp_commit();
        cp_wait<0>();
        __syncthreads();
        const int r = tid >> 5, b = tid & 31;
        const float* wr = ws + r * 516;
        float acc = 0.f;
        #pragma unroll 8
        for (int k = 0; k < HH; k++) acc += xs[k * 32 + b] * wr[k];
        __stcg(&dst[b * HH + d0 + r], acc + bias[d0 + r]);
        __syncthreads();
    }
}

// ---- attention: 2 half-block units per CTA (proven) ----
__device__ void attn_phase(char* smem) {
    float (*qsm)[64]     = (float(*)[64])smem;
    float (*sc)[128]     = (float(*)[128])(smem + 512);
    float (*red)[8]      = (float(*)[8])(smem + 512 + 1024);
    float (*pav)[2][64]  = (float(*)[2][64])(smem + 512 + 1024 + 64);
    const int tid = threadIdx.x;
    const int h = tid >> 7, wt = tid & 127;
    const int lane = tid & 31, w4 = (tid >> 5) & 3;
    for (int ub = blockIdx.x * 2; ub < 256; ub += gridDim.x * 2) {
        const int u = ub + h;
        const int b = u >> 3, hd = u & 7;
        if (hd == 0 && wt == 0) { __stcg(&g_amax[b], 0ull); __stcg(&g_packed[b], 0ull); }
        if (wt < 64) qsm[h][wt] = __ldcg(&g_q[b][hd * 64 + wt]);
        __syncthreads();
        {
            const float4* kr = (const float4*)&g_k[b][wt][hd * 64];
            const float4* q4 = (const float4*)qsm[h];
            float acc = 0.f;
            #pragma unroll
            for (int d4 = 0; d4 < 16; d4++) {
                float4 kv = kr[d4], qv = q4[d4];
                acc += qv.x * kv.x + qv.y * kv.y + qv.z * kv.z + qv.w * kv.w;
            }
            sc[h][wt] = acc * 0.125f;
        }
        __syncthreads();
        if (wt < 32) {
            float m = fmaxf(fmaxf(sc[h][wt], sc[h][wt + 32]), fmaxf(sc[h][wt + 64], sc[h][wt + 96]));
            #pragma unroll
            for (int off = 16; off; off >>= 1) m = fmaxf(m, __shfl_xor_sync(0xffffffffu, m, off));
            if (lane == 0) red[h][0] = m;
        }
        __syncthreads();
        float mm = red[h][0];
        {
            float e = expf(sc[h][wt] - mm);
            sc[h][wt] = e;
            float s = e;
            #pragma unroll
            for (int off = 16; off; off >>= 1) s += __shfl_xor_sync(0xffffffffu, s, off);
            if (lane == 0) red[h][1 + w4] = s;
        }
        __syncthreads();
        float tot = red[h][1] + red[h][2] + red[h][3] + red[h][4];
        {
            int d = wt & 63, sg = wt >> 6;
            float acc = 0.f;
            #pragma unroll 8
            for (int s5 = 0; s5 < 64; s5++) {
                int s = sg * 64 + s5;
                acc += sc[h][s] * g_v[b][s][hd * 64 + d];
            }
            pav[h][sg][d] = acc;
        }
        __syncthreads();
        if (wt < 64)
            __stcg(&g_attnT[hd * 64 + wt][b], (pav[h][0][wt] + pav[h][1][wt]) / tot);
        __syncthreads();
    }
}

// ---- logits: mma bf16-split, cp.async double-buffered B (proven) ----
__device__ void logits_phase(char* smem, const float* __restrict__ bout,
                             float* __restrict__ out, int t) {
    __nv_bfloat16* As = (__nv_bfloat16*)smem;
    const uint32_t bbase[2] = {smem_u32(smem + L_ABYTES), smem_u32(smem + L_ABYTES + L_BBUF)};
    unsigned long long* skey = (unsigned long long*)(smem + L_ABYTES + 2 * L_BBUF);
    const int tid = threadIdx.x, lane = tid & 31, w = tid >> 5;
    const uint32_t as_u = smem_u32(As);

    for (int tile = blockIdx.x; tile < 125; tile += gridDim.x) {
        const int n0 = tile * 256;
        if (tid < 32) skey[tid] = 0ull;

        auto issueB = [&](int c, int buf) {
            #pragma unroll
            for (int j = 0; j < 8; j++) {
                int e = j * 256 + tid;
                int rr = e >> 2, q = e & 3;
                const __nv_bfloat16* src = (rr & 256) ? g_wl : g_wh;
                cp16(bbase[buf] + rr * 80 + q * 16,
                     src + (size_t)(n0 + (rr & 255)) * HH + c * 32 + q * 8);
            }
            cp_commit();
        };
        issueB(0, 0);
        issueB(1, 1);

        for (int i2 = tid; i2 < 32 * HH; i2 += 256) {
            int m = i2 >> 9, k = i2 & 511;
            float x = __ldcg(&g_attno[m][k]);
            __nv_bfloat16 hb = __float2bfloat16(x);
            As[m * ASTRIDE + k] = hb;
            As[(32 + m) * ASTRIDE + k] = __float2bfloat16(x - __bfloat162float(hb));
        }

        float acc[2][4][4] = {};
        for (int kc = 0; kc < 16; kc++) {
            if (kc == 15) cp_wait<0>(); else cp_wait<1>();
            __syncthreads();
            const uint32_t bu = bbase[kc & 1];
            #pragma unroll
            for (int kk = 0; kk < 32; kk += 16) {
                const int ka = kc * 32 + kk;
                uint32_t ah[2][4], al[2][4], bh[4][2], bl[4][2];
                #pragma unroll
                for (int mt = 0; mt < 2; mt++) {
                    int r = mt * 16 + (lane & 15);
                    int k = ka + (((lane >> 4) & 1) << 3);
                    ldsm_x4(ah[mt], as_u + (r * ASTRIDE + k) * 2);
                    ldsm_x4(al[mt], as_u + ((32 + r) * ASTRIDE + k) * 2);
                }
                #pragma unroll
                for (int nt = 0; nt < 4; nt++) {
                    int nrow = w * 32 + nt * 8 + (lane & 7);
                    int k = kk + ((lane & 8) ? 8 : 0);
                    ldsm_x2(bh[nt], bu + nrow * 80 + k * 2);
                    ldsm_x2(bl[nt], bu + (256 + nrow) * 80 + k * 2);
                }
                #pragma unroll
                for (int mt = 0; mt < 2; mt++)
                    #pragma unroll
                    for (int nt = 0; nt < 4; nt++) {
                        mma_bf16(acc[mt][nt], ah[mt], bh[nt]);
                        mma_bf16(acc[mt][nt], ah[mt], bl[nt]);
                        mma_bf16(acc[mt][nt], al[mt], bh[nt]);
                    }
            }
            __syncthreads();
            if (kc + 2 < 16) issueB(kc + 2, kc & 1);
        }

        unsigned long long lkey[2][2] = {{0ull, 0ull}, {0ull, 0ull}};
        #pragma unroll
        for (int mt = 0; mt < 2; mt++)
            #pragma unroll
            for (int nt = 0; nt < 4; nt++) {
                int n = n0 + w * 32 + nt * 8 + (lane & 3) * 2;
                float2 bias = *(const float2*)&bout[n];
                #pragma unroll
                for (int h = 0; h < 2; h++) {
                    int b = mt * 16 + (lane >> 2) + h * 8;
                    float2 v;
                    v.x = acc[mt][nt][h * 2] + bias.x;
                    v.y = acc[mt][nt][h * 2 + 1] + bias.y;
                    *(float2*)&out[((size_t)b * SS + t + 1) * VV + n] = v;
                    unsigned long long k1 = amax_key(v.x, n);
                    unsigned long long k2 = amax_key(v.y, n + 1);
                    if (k2 > k1) k1 = k2;
                    if (k1 > lkey[mt][h]) lkey[mt][h] = k1;
                }
            }
        #pragma unroll
        for (int mt = 0; mt < 2; mt++)
            #pragma unroll
            for (int h = 0; h < 2; h++) {
                unsigned long long kk = lkey[mt][h];
                unsigned long long o = __shfl_xor_sync(0xffffffffu, kk, 1); if (o > kk) kk = o;
                o = __shfl_xor_sync(0xffffffffu, kk, 2); if (o > kk) kk = o;
                if ((lane & 3) == 0) atomicMax(&skey[mt * 16 + (lane >> 2) + h * 8], kk);
            }
        __syncthreads();
        if (tid < 32 && skey[tid]) atomicMax(&g_amax[tid], skey[tid]);
        __syncthreads();
    }
}

// ---- fix: 128 (b, quarter) units; fp32-exact argmax among candidates ----
__device__ void fix_phase(char* smem, const float* __restrict__ Wout,
                          const float* __restrict__ bout,
                          const float* __restrict__ out, int t) {
    float* ax = (float*)smem;
    const int tid = threadIdx.x, lane = tid & 31;
    for (int u = blockIdx.x; u < 128; u += gridDim.x) {
        const int b = u >> 2, qtr = u & 3;
        for (int d = tid; d < HH; d += 256) ax[d] = __ldcg(&g_attno[b][d]);
        __syncthreads();
        unsigned long long ak = __ldcg(&g_amax[b]);
        unsigned ue = (unsigned)(ak >> 32);
        unsigned uv = (ue & 0x80000000u) ? (ue & 0x7fffffffu) : ~ue;
        const float thr = __uint_as_float(uv) - 1e-2f;
        const float* row = out + ((size_t)b * SS + t + 1) * VV;
        unsigned long long best = 0ull;
        for (int n4 = qtr * 2000 + tid; n4 < (qtr + 1) * 2000; n4 += 256) {
            float4 v = __ldcg((const float4*)&row[n4 * 4]);
            float mv = fmaxf(fmaxf(v.x, v.y), fmaxf(v.z, v.w));
            if (mv >= thr) {
                float vv[4] = {v.x, v.y, v.z, v.w};
                #pragma unroll
                for (int j = 0; j < 4; j++) {
                    if (vv[j] >= thr) {
                        int n = n4 * 4 + j;
                        const float* wr = Wout + (size_t)n * HH;
                        float d = 0.f;
                        for (int k = 0; k < HH; k++) d += ax[k] * wr[k];
                        unsigned long long key = amax_key(d + bout[n], n);
                        if (key > best) best = key;
                    }
                }
            }
        }
        #pragma unroll
        for (int off = 16; off; off >>= 1) {
            unsigned long long o = __shfl_xor_sync(0xffffffffu, best, off);
            if (o > best) best = o;
        }
        __syncthreads();
        if (lane == 0 && best) atomicMax(&g_packed[b], best);
        __syncthreads();
    }
}

__global__ void __launch_bounds__(256, 1)
decoder_persist(const float* __restrict__ b_ih, const float* __restrict__ b_hh,
                const float* __restrict__ Wq, const float* __restrict__ bq,
                const float* __restrict__ Wo, const float* __restrict__ bo,
                const float* __restrict__ W_out, const float* __restrict__ b_out,
                float* __restrict__ out) {
    extern __shared__ char smem[];
    unsigned ep = 0;
    for (int t = 0; t < NSTEP; t++) {
        const int pin = t & 1, pout = pin ^ 1;
        lstm_phase(0, pin, t == 0, smem, b_ih, b_hh);
        gridbar(++ep);
        lstm_phase(1, pin, 0, smem, b_ih, b_hh);
        gridbar(++ep);
        gemm512_phase(smem, &g_h[pout][1][0][0], Wq, bq, &g_q[0][0]);
        gridbar(++ep);
        attn_phase(smem);
        gridbar(++ep);
        gemm512_phase(smem, &g_attnT[0][0], Wo, bo, &g_attno[0][0]);
        gridbar(++ep);
        logits_phase(smem, b_out, out, t);
        gridbar(++ep);
        fix_phase(smem, W_out, b_out, out, t);
        gridbar(++ep);
    }
}

extern "C" void kernel_launch(void* const* d_in, const int* in_sizes, int n_in,
                              void* d_out, int out_size) {
    const float* hs     = (const float*)d_in[0];
    const float* hidden = (const float*)d_in[1];
    const float* cell   = (const float*)d_in[2];
    const float* emb    = (const float*)d_in[3];
    const float* W_ih   = (const float*)d_in[4];
    const float* W_hh   = (const float*)d_in[5];
    const float* b_ih   = (const float*)d_in[6];
    const float* b_hh   = (const float*)d_in[7];
    const float* Wq     = (const float*)d_in[8];
    const float* bq     = (const float*)d_in[9];
    const float* Wk     = (const float*)d_in[10];
    const float* bk     = (const float*)d_in[11];
    const float* Wv     = (const float*)d_in[12];
    const float* bv     = (const float*)d_in[13];
    const float* Wo     = (const float*)d_in[14];
    const float* bo     = (const float*)d_in[15];
    const float* W_out  = (const float*)d_in[16];
    const float* b_out  = (const float*)d_in[17];
    float* out = (float*)d_out;

    cudaFuncSetAttribute(decoder_persist, cudaFuncAttributeMaxDynamicSharedMemorySize, SMEM_DYN);

    init_kernel<<<4000, 256>>>(hidden, cell, W_out, emb, W_ih, W_hh, out);

    dim3 kvg(128, 4);
    kv_kernel<<<kvg, 256>>>(hs, Wk, bk, 0);
    kv_kernel<<<kvg, 256>>>(hs, Wv, bv, 1);

    decoder_persist<<<NCTA, 256, SMEM_DYN>>>(b_ih, b_hh, Wq, bq, Wo, bo, W_out, b_out, out);
}

// round 15
// speedup vs baseline: 1.3252x; 1.0300x over previous
#include <cuda_runtime.h>
#include <cuda_bf16.h>
#include <cstdint>

#define SB 32
#define SS 128
#define HH 512
#define VV 32000
#define NSTEP 127
#define NCTA 148

__device__ float g_h[2][2][HH][SB];
__device__ float g_c[2][2][HH][SB];
__device__ __nv_bfloat16 g_hsp[2][2][2][SB][HH];  // [pp][layer][hi/lo][b][dim]
__device__ float g_k[SB][SS][HH];
__device__ float g_v[SB][SS][HH];
__device__ float g_q[SB][HH];
__device__ float g_attnT[HH][SB];
__device__ float g_attno[SB][HH];
__device__ unsigned long long g_amax[SB];
__device__ unsigned long long g_packed[SB];
__device__ __nv_bfloat16 g_wh[(size_t)VV * HH];
__device__ __nv_bfloat16 g_wl[(size_t)VV * HH];
__device__ __nv_bfloat16 g_embh[(size_t)VV * HH];
__device__ __nv_bfloat16 g_embl[(size_t)VV * HH];
__device__ __nv_bfloat16 g_lwh[2][4 * HH][2 * HH];
__device__ __nv_bfloat16 g_lwl[2][4 * HH][2 * HH];
__device__ unsigned g_arr[NCTA];
__device__ unsigned g_rel[NCTA];

__device__ __forceinline__ float sigf(float x) { return 1.f / (1.f + expf(-x)); }
__device__ __forceinline__ unsigned long long amax_key(float v, int n) {
    unsigned u = __float_as_uint(v);
    u = (u & 0x80000000u) ? ~u : (u | 0x80000000u);
    return ((unsigned long long)u << 32) | (unsigned)(~(unsigned)n);
}

// two-hop atomic flag-array grid barrier (proven-good)
__device__ __forceinline__ void gridbar(unsigned ep) {
    __syncthreads();
    if (blockIdx.x == 0) {
        if (threadIdx.x == 0) __threadfence();
        __syncthreads();
        if (threadIdx.x > 0 && threadIdx.x < NCTA) {
            while (atomicAdd(&g_arr[threadIdx.x], 0u) < ep) { }
        }
        __syncthreads();
        if (threadIdx.x == 0) __threadfence();
        __syncthreads();
        if (threadIdx.x < NCTA) atomicExch(&g_rel[threadIdx.x], ep);
    } else {
        if (threadIdx.x == 0) {
            __threadfence();
            atomicExch(&g_arr[blockIdx.x], ep);
            while (atomicAdd(&g_rel[blockIdx.x], 0u) < ep) { }
        }
    }
    __syncthreads();
}

__device__ __forceinline__ uint32_t smem_u32(const void* p) {
    uint32_t a;
    asm("{ .reg .u64 t; cvta.to.shared.u64 t, %1; cvt.u32.u64 %0, t; }" : "=r"(a) : "l"(p));
    return a;
}
__device__ __forceinline__ void ldsm_x4(uint32_t* r, uint32_t addr) {
    asm volatile("ldmatrix.sync.aligned.m8n8.x4.shared.b16 {%0,%1,%2,%3}, [%4];"
                 : "=r"(r[0]), "=r"(r[1]), "=r"(r[2]), "=r"(r[3]) : "r"(addr));
}
__device__ __forceinline__ void ldsm_x2(uint32_t* r, uint32_t addr) {
    asm volatile("ldmatrix.sync.aligned.m8n8.x2.shared.b16 {%0,%1}, [%2];"
                 : "=r"(r[0]), "=r"(r[1]) : "r"(addr));
}
__device__ __forceinline__ void mma_bf16(float* c, const uint32_t* a, const uint32_t* b) {
    asm volatile(
        "mma.sync.aligned.m16n8k16.row.col.f32.bf16.bf16.f32 "
        "{%0,%1,%2,%3}, {%4,%5,%6,%7}, {%8,%9}, {%0,%1,%2,%3};"
        : "+f"(c[0]), "+f"(c[1]), "+f"(c[2]), "+f"(c[3])
        : "r"(a[0]), "r"(a[1]), "r"(a[2]), "r"(a[3]), "r"(b[0]), "r"(b[1]));
}
__device__ __forceinline__ void cp16(uint32_t dst, const void* src) {
    asm volatile("cp.async.cg.shared.global [%0], [%1], 16;" :: "r"(dst), "l"(src));
}
__device__ __forceinline__ void cp_commit() { asm volatile("cp.async.commit_group;" ::: "memory"); }
template <int N>
__device__ __forceinline__ void cp_wait() { asm volatile("cp.async.wait_group %0;" :: "n"(N) : "memory"); }

#define ASTRIDE 520
#define L_ABYTES (64 * ASTRIDE * 2)              // 66560
#define L_BBUF   40960                            // 512 rows x 80B
#define SMEM_DYN (L_ABYTES + 2 * L_BBUF + 512)    // 148992

__global__ void init_kernel(const float* __restrict__ hidden, const float* __restrict__ cell,
                            const float* __restrict__ W_out, const float* __restrict__ emb,
                            const float* __restrict__ W_ih, const float* __restrict__ W_hh,
                            float* __restrict__ out) {
    const int idx = blockIdx.x * blockDim.x + threadIdx.x;
    const size_t stride = (size_t)gridDim.x * blockDim.x;
    if (idx < NCTA) { g_arr[idx] = 0; g_rel[idx] = 0; }
    if (idx < 2 * SB * HH) {
        int l = idx >> 14, b = (idx >> 9) & 31, h = idx & 511;
        float hv = hidden[idx];
        g_h[0][l][h][b] = hv;
        g_c[0][l][h][b] = cell[idx];
        __nv_bfloat16 hb = __float2bfloat16(hv);
        g_hsp[0][l][0][b][h] = hb;
        g_hsp[0][l][1][b][h] = __float2bfloat16(hv - __bfloat162float(hb));
    }
    if (idx < SB * VV) {
        int b = idx / VV, v = idx % VV;
        out[(size_t)b * SS * VV + v] = 0.f;
    }
    const size_t nw = (size_t)VV * HH;
    for (size_t i = idx; i < nw; i += stride) {
        float w = W_out[i];
        __nv_bfloat16 h = __float2bfloat16(w);
        g_wh[i] = h;
        g_wl[i] = __float2bfloat16(w - __bfloat162float(h));
        float e = emb[i];
        __nv_bfloat16 eh = __float2bfloat16(e);
        g_embh[i] = eh;
        g_embl[i] = __float2bfloat16(e - __bfloat162float(eh));
    }
    const size_t nlw = (size_t)2 * 4 * HH * 2 * HH;
    for (size_t i = idx; i < nlw; i += stride) {
        int l = (int)(i >> 21);
        int rem = (int)(i & ((1u << 21) - 1));
        int n = rem >> 10, k = rem & 1023;
        float w = (k < HH) ? W_ih[((size_t)l * 4 * HH + n) * HH + k]
                           : W_hh[((size_t)l * 4 * HH + n) * HH + (k - HH)];
        __nv_bfloat16 h = __float2bfloat16(w);
        g_lwh[l][n][k] = h;
        g_lwl[l][n][k] = __float2bfloat16(w - __bfloat162float(h));
    }
}

__global__ void kv_kernel(const float* __restrict__ hs, const float* __restrict__ W,
                          const float* __restrict__ bias, int which) {
    __shared__ float Ash[32][36];
    __shared__ float Wsh[32][132];
    float* dst = which ? &g_v[0][0][0] : &g_k[0][0][0];
    const int r0 = blockIdx.x * 32, n0 = blockIdx.y * 128;
    const int tid = threadIdx.x, lane = tid & 31, grp = tid >> 5;
    float acc[4][4] = {};
    for (int k0 = 0; k0 < HH; k0 += 32) {
        #pragma unroll
        for (int j = 0; j < 4; j++) {
            int m = grp + j * 8, r = r0 + m;
            Ash[lane][m] = hs[(size_t)(r & 127) * (SB * HH) + (r >> 7) * HH + k0 + lane];
        }
        #pragma unroll
        for (int j = 0; j < 16; j++) {
            int nn = grp + j * 8;
            Wsh[lane][nn] = W[(size_t)(n0 + nn) * HH + k0 + lane];
        }
        __syncthreads();
        #pragma unroll
        for (int k = 0; k < 32; k++) {
            float4 a4 = *(const float4*)&Ash[k][grp * 4];
            float4 w4 = *(const float4*)&Wsh[k][lane * 4];
            acc[0][0] += a4.x * w4.x; acc[0][1] += a4.x * w4.y; acc[0][2] += a4.x * w4.z; acc[0][3] += a4.x * w4.w;
            acc[1][0] += a4.y * w4.x; acc[1][1] += a4.y * w4.y; acc[1][2] += a4.y * w4.z; acc[1][3] += a4.y * w4.w;
            acc[2][0] += a4.z * w4.x; acc[2][1] += a4.z * w4.y; acc[2][2] += a4.z * w4.z; acc[2][3] += a4.z * w4.w;
            acc[3][0] += a4.w * w4.x; acc[3][1] += a4.w * w4.y; acc[3][2] += a4.w * w4.z; acc[3][3] += a4.w * w4.w;
        }
        __syncthreads();
    }
    const int nbase = n0 + lane * 4;
    float4 b4 = *(const float4*)&bias[nbase];
    #pragma unroll
    for (int i = 0; i < 4; i++) {
        int r = r0 + grp * 4 + i;
        float4 v;
        v.x = acc[i][0] + b4.x; v.y = acc[i][1] + b4.y;
        v.z = acc[i][2] + b4.z; v.w = acc[i][3] + b4.w;
        *(float4*)&dst[(size_t)r * HH + nbase] = v;
    }
}

// ---- LSTM: 128 tiles x np=4; warps m2 x n2 x k2; bf16 4-product; 4-deep cp.async ----
__device__ void lstm_phase(int layer, int pin, int first, char* smem,
                           const float* __restrict__ b_ih, const float* __restrict__ b_hh) {
    const int tid = threadIdx.x, lane = tid & 31, w = tid >> 5;
    const int pout = pin ^ 1;
    uint32_t abase[4], wbase[4];
    #pragma unroll
    for (int i = 0; i < 4; i++) {
        abase[i] = smem_u32(smem + i * 17408);
        wbase[i] = smem_u32(smem + 69632 + i * 8704);
    }
    float (*Dsh)[16][33] = (float(*)[16][33])(smem + 104448);
    int* tok_s = (int*)(smem + 104448 + 4224);

    for (int tile = blockIdx.x; tile < 128; tile += gridDim.x) {
        const int np0 = tile * 4;
        if (tid < SB) {
            if (first) tok_s[tid] = 0;
            else tok_s[tid] = (int)(~(unsigned)(__ldcg(&g_packed[tid]) & 0xFFFFFFFFull));
        }
        __syncthreads();
        const int arow = tid >> 2, aseg = (tid & 3) * 64;
        const int wrow = tid >> 3, wseg = (tid & 7) * 32;

        auto issue = [&](int c, int buf) {
            const __nv_bfloat16* asrc;
            int s = arow >> 5, b = arow & 31, k0 = c * 128;
            if (k0 < HH) {
                if (layer == 0) asrc = (s ? g_embl : g_embh) + (size_t)tok_s[b] * HH + k0;
                else asrc = &g_hsp[pout][0][s][b][k0];
            } else asrc = &g_hsp[pin][layer][s][b][k0 - HH];
            uint32_t ad = abase[buf] + arow * 272 + aseg;
            const char* ap = (const char*)asrc + aseg;
            #pragma unroll
            for (int j = 0; j < 4; j++) cp16(ad + j * 16, ap + j * 16);
            int ws = wrow >> 4, nl = wrow & 15;
            int n = (nl >> 2) * HH + np0 + (nl & 3);
            const __nv_bfloat16* wsrc = (ws ? &g_lwl[layer][n][0] : &g_lwh[layer][n][0]) + c * 128;
            uint32_t wd = wbase[buf] + wrow * 272 + wseg;
            const char* wp = (const char*)wsrc + wseg;
            cp16(wd, wp);
            cp16(wd + 16, wp + 16);
            cp_commit();
        };

        issue(0, 0); issue(1, 1); issue(2, 2);
        const int om = w & 1, nt = (w >> 1) & 1, kh = w >> 2;
        float acc[4] = {0.f, 0.f, 0.f, 0.f};
        for (int c = 0; c < 8; c++) {
            if (c + 3 < 8) issue(c + 3, (c + 3) & 3);
            if (c <= 4) cp_wait<3>();
            else if (c == 5) cp_wait<2>();
            else if (c == 6) cp_wait<1>();
            else cp_wait<0>();
            __syncthreads();
            const uint32_t au = abase[c & 3], wu = wbase[c & 3];
            #pragma unroll
            for (int kj = 0; kj < 4; kj++) {
                int kt = kh * 4 + kj;
                uint32_t ah[4], al[4], wh[2], wl[2];
                int ar = om * 16 + (lane & 15);
                int kb = kt * 16 + ((lane >> 4) << 3);
                ldsm_x4(ah, au + ar * 272 + kb * 2);
                ldsm_x4(al, au + (ar + 32) * 272 + kb * 2);
                int wr = nt * 8 + (lane & 7);
                int kb2 = kt * 16 + ((lane & 8) ? 8 : 0);
                ldsm_x2(wh, wu + wr * 272 + kb2 * 2);
                ldsm_x2(wl, wu + (wr + 16) * 272 + kb2 * 2);
                mma_bf16(acc, ah, wh);
                mma_bf16(acc, ah, wl);
                mma_bf16(acc, al, wh);
                mma_bf16(acc, al, wl);
            }
            __syncthreads();
        }
        #pragma unroll
        for (int ci = 0; ci < 4; ci++) {
            int b = om * 16 + (lane >> 2) + ((ci >> 1) << 3);
            int nl = nt * 8 + (lane & 3) * 2 + (ci & 1);
            Dsh[kh][nl][b] = acc[ci];
        }
        __syncthreads();
        if (tid < 128) {
            int i = tid >> 5, b = tid & 31, np = np0 + i;
            const size_t bo = (size_t)layer * 4 * HH;
            float s[4];
            #pragma unroll
            for (int g = 0; g < 4; g++)
                s[g] = Dsh[0][g * 4 + i][b] + Dsh[1][g * 4 + i][b]
                     + b_ih[bo + g * HH + np] + b_hh[bo + g * HH + np];
            float cold = __ldcg(&g_c[pin][layer][np][b]);
            float cn = sigf(s[1]) * cold + sigf(s[0]) * tanhf(s[2]);
            float hn = sigf(s[3]) * tanhf(cn);
            __stcg(&g_c[pout][layer][np][b], cn);
            __stcg(&g_h[pout][layer][np][b], hn);
            __nv_bfloat16 hb = __float2bfloat16(hn);
            g_hsp[pout][layer][0][b][np] = hb;
            g_hsp[pout][layer][1][b][np] = __float2bfloat16(hn - __bfloat162float(hb));
        }
        __syncthreads();
    }
}

// ---- generic 512x512 projection: 128 tiles x 4 dims, warp = (row, k-half) ----
__device__ void gemm512_phase(char* smem, const float* __restrict__ src,
                              const float* __restrict__ W, const float* __restrict__ bias,
                              float* __restrict__ dst) {
    float* xs = (float*)smem;                        // [512*32] floats
    float* ws = (float*)(smem + 65536);              // [4][516]
    float* part = (float*)(smem + 65536 + 8256);     // [8][32]
    const int tid = threadIdx.x, lane = tid & 31, w = tid >> 5;
    const uint32_t xu = smem_u32(xs), wu = smem_u32(ws);
    for (int tile = blockIdx.x; tile < 128; tile += gridDim.x) {
        const int d0 = tile * 4;
        #pragma unroll
        for (int j = 0; j < 16; j++) {
            int e = tid + j * 256;
            cp16(xu + e * 16, (const char*)src + e * 16);
        }
        #pragma unroll
        for (int j = 0; j < 2; j++) {
            int e = tid + j * 256;
            int row = e >> 7, seg = e & 127;
            cp16(wu + row * 2064 + seg * 16, W + (size_t)(d0 + row) * HH + seg * 4);
        }
        cp_commit();
        cp_wait<0>();
        __syncthreads();
        const int r = w >> 1, kh = w & 1;
        const float* wr = ws + r * 516 + kh * 256;
        const float* xp = xs + kh * 256 * 32;
        float acc = 0.f;
        #pragma unroll 8
        for (int k = 0; k < 256; k++) acc += xp[k * 32 + lane] * wr[k];
        part[w * 32 + lane] = acc;
        __syncthreads();
        if (tid < 128) {
            int rr = tid >> 5, b = tid & 31;
            float v = part[(rr * 2) * 32 + b] + part[(rr * 2 + 1) * 32 + b];
            __stcg(&dst[b * HH + d0 + rr], v + bias[d0 + rr]);
        }
        __syncthreads();
    }
}

// ---- attention: 2 half-block units per CTA (proven) ----
__device__ void attn_phase(char* smem) {
    float (*qsm)[64]     = (float(*)[64])smem;
    float (*sc)[128]     = (float(*)[128])(smem + 512);
    float (*red)[8]      = (float(*)[8])(smem + 512 + 1024);
    float (*pav)[2][64]  = (float(*)[2][64])(smem + 512 + 1024 + 64);
    const int tid = threadIdx.x;
    const int h = tid >> 7, wt = tid & 127;
    const int lane = tid & 31, w4 = (tid >> 5) & 3;
    for (int ub = blockIdx.x * 2; ub < 256; ub += gridDim.x * 2) {
        const int u = ub + h;
        const int b = u >> 3, hd = u & 7;
        if (hd == 0 && wt == 0) { __stcg(&g_amax[b], 0ull); __stcg(&g_packed[b], 0ull); }
        if (wt < 64) qsm[h][wt] = __ldcg(&g_q[b][hd * 64 + wt]);
        __syncthreads();
        {
            const float4* kr = (const float4*)&g_k[b][wt][hd * 64];
            const float4* q4 = (const float4*)qsm[h];
            float acc = 0.f;
            #pragma unroll
            for (int d4 = 0; d4 < 16; d4++) {
                float4 kv = kr[d4], qv = q4[d4];
                acc += qv.x * kv.x + qv.y * kv.y + qv.z * kv.z + qv.w * kv.w;
            }
            sc[h][wt] = acc * 0.125f;
        }
        __syncthreads();
        if (wt < 32) {
            float m = fmaxf(fmaxf(sc[h][wt], sc[h][wt + 32]), fmaxf(sc[h][wt + 64], sc[h][wt + 96]));
            #pragma unroll
            for (int off = 16; off; off >>= 1) m = fmaxf(m, __shfl_xor_sync(0xffffffffu, m, off));
            if (lane == 0) red[h][0] = m;
        }
        __syncthreads();
        float mm = red[h][0];
        {
            float e = expf(sc[h][wt] - mm);
            sc[h][wt] = e;
            float s = e;
            #pragma unroll
            for (int off = 16; off; off >>= 1) s += __shfl_xor_sync(0xffffffffu, s, off);
            if (lane == 0) red[h][1 + w4] = s;
        }
        __syncthreads();
        float tot = red[h][1] + red[h][2] + red[h][3] + red[h][4];
        {
            int d = wt & 63, sg = wt >> 6;
            float acc = 0.f;
            #pragma unroll 8
            for (int s5 = 0; s5 < 64; s5++) {
                int s = sg * 64 + s5;
                acc += sc[h][s] * g_v[b][s][hd * 64 + d];
            }
            pav[h][sg][d] = acc;
        }
        __syncthreads();
        if (wt < 64)
            __stcg(&g_attnT[hd * 64 + wt][b], (pav[h][0][wt] + pav[h][1][wt]) / tot);
        __syncthreads();
    }
}

// ---- logits: mma bf16-split, cp.async double-buffered B (proven) ----
__device__ void logits_phase(char* smem, const float* __restrict__ bout,
                             float* __restrict__ out, int t) {
    __nv_bfloat16* As = (__nv_bfloat16*)smem;
    const uint32_t bbase[2] = {smem_u32(smem + L_ABYTES), smem_u32(smem + L_ABYTES + L_BBUF)};
    unsigned long long* skey = (unsigned long long*)(smem + L_ABYTES + 2 * L_BBUF);
    const int tid = threadIdx.x, lane = tid & 31, w = tid >> 5;
    const uint32_t as_u = smem_u32(As);

    for (int tile = blockIdx.x; tile < 125; tile += gridDim.x) {
        const int n0 = tile * 256;
        if (tid < 32) skey[tid] = 0ull;

        auto issueB = [&](int c, int buf) {
            #pragma unroll
            for (int j = 0; j < 8; j++) {
                int e = j * 256 + tid;
                int rr = e >> 2, q = e & 3;
                const __nv_bfloat16* src = (rr & 256) ? g_wl : g_wh;
                cp16(bbase[buf] + rr * 80 + q * 16,
                     src + (size_t)(n0 + (rr & 255)) * HH + c * 32 + q * 8);
            }
            cp_commit();
        };
        issueB(0, 0);
        issueB(1, 1);

        for (int i2 = tid; i2 < 32 * HH; i2 += 256) {
            int m = i2 >> 9, k = i2 & 511;
            float x = __ldcg(&g_attno[m][k]);
            __nv_bfloat16 hb = __float2bfloat16(x);
            As[m * ASTRIDE + k] = hb;
            As[(32 + m) * ASTRIDE + k] = __float2bfloat16(x - __bfloat162float(hb));
        }

        float acc[2][4][4] = {};
        for (int kc = 0; kc < 16; kc++) {
            if (kc == 15) cp_wait<0>(); else cp_wait<1>();
            __syncthreads();
            const uint32_t bu = bbase[kc & 1];
            #pragma unroll
            for (int kk = 0; kk < 32; kk += 16) {
                const int ka = kc * 32 + kk;
                uint32_t ah[2][4], al[2][4], bh[4][2], bl[4][2];
                #pragma unroll
                for (int mt = 0; mt < 2; mt++) {
                    int r = mt * 16 + (lane & 15);
                    int k = ka + (((lane >> 4) & 1) << 3);
                    ldsm_x4(ah[mt], as_u + (r * ASTRIDE + k) * 2);
                    ldsm_x4(al[mt], as_u + ((32 + r) * ASTRIDE + k) * 2);
                }
                #pragma unroll
                for (int nt = 0; nt < 4; nt++) {
                    int nrow = w * 32 + nt * 8 + (lane & 7);
                    int k = kk + ((lane & 8) ? 8 : 0);
                    ldsm_x2(bh[nt], bu + nrow * 80 + k * 2);
                    ldsm_x2(bl[nt], bu + (256 + nrow) * 80 + k * 2);
                }
                #pragma unroll
                for (int mt = 0; mt < 2; mt++)
                    #pragma unroll
                    for (int nt = 0; nt < 4; nt++) {
                        mma_bf16(acc[mt][nt], ah[mt], bh[nt]);
                        mma_bf16(acc[mt][nt], ah[mt], bl[nt]);
                        mma_bf16(acc[mt][nt], al[mt], bh[nt]);
                    }
            }
            __syncthreads();
            if (kc + 2 < 16) issueB(kc + 2, kc & 1);
        }

        unsigned long long lkey[2][2] = {{0ull, 0ull}, {0ull, 0ull}};
        #pragma unroll
        for (int mt = 0; mt < 2; mt++)
            #pragma unroll
            for (int nt = 0; nt < 4; nt++) {
                int n = n0 + w * 32 + nt * 8 + (lane & 3) * 2;
                float2 bias = *(const float2*)&bout[n];
                #pragma unroll
                for (int h = 0; h < 2; h++) {
                    int b = mt * 16 + (lane >> 2) + h * 8;
                    float2 v;
                    v.x = acc[mt][nt][h * 2] + bias.x;
                    v.y = acc[mt][nt][h * 2 + 1] + bias.y;
                    *(float2*)&out[((size_t)b * SS + t + 1) * VV + n] = v;
                    unsigned long long k1 = amax_key(v.x, n);
                    unsigned long long k2 = amax_key(v.y, n + 1);
                    if (k2 > k1) k1 = k2;
                    if (k1 > lkey[mt][h]) lkey[mt][h] = k1;
                }
            }
        #pragma unroll
        for (int mt = 0; mt < 2; mt++)
            #pragma unroll
            for (int h = 0; h < 2; h++) {
                unsigned long long kk = lkey[mt][h];
                unsigned long long o = __shfl_xor_sync(0xffffffffu, kk, 1); if (o > kk) kk = o;
                o = __shfl_xor_sync(0xffffffffu, kk, 2); if (o > kk) kk = o;
                if ((lane & 3) == 0) atomicMax(&skey[mt * 16 + (lane >> 2) + h * 8], kk);
            }
        __syncthreads();
        if (tid < 32 && skey[tid]) atomicMax(&g_amax[tid], skey[tid]);
        __syncthreads();
    }
}

// ---- fix: 128 (b, quarter) units; fp32-exact argmax among candidates ----
__device__ void fix_phase(char* smem, const float* __restrict__ Wout,
                          const float* __restrict__ bout,
                          const float* __restrict__ out, int t) {
    float* ax = (float*)smem;
    const int tid = threadIdx.x, lane = tid & 31;
    for (int u = blockIdx.x; u < 128; u += gridDim.x) {
        const int b = u >> 2, qtr = u & 3;
        for (int d = tid; d < HH; d += 256) ax[d] = __ldcg(&g_attno[b][d]);
        __syncthreads();
        unsigned long long ak = __ldcg(&g_amax[b]);
        unsigned ue = (unsigned)(ak >> 32);
        unsigned uv = (ue & 0x80000000u) ? (ue & 0x7fffffffu) : ~ue;
        const float thr = __uint_as_float(uv) - 1e-2f;
        const float* row = out + ((size_t)b * SS + t + 1) * VV;
        unsigned long long best = 0ull;
        for (int n4 = qtr * 2000 + tid; n4 < (qtr + 1) * 2000; n4 += 256) {
            float4 v = __ldcg((const float4*)&row[n4 * 4]);
            float mv = fmaxf(fmaxf(v.x, v.y), fmaxf(v.z, v.w));
            if (mv >= thr) {
                float vv[4] = {v.x, v.y, v.z, v.w};
                #pragma unroll
                for (int j = 0; j < 4; j++) {
                    if (vv[j] >= thr) {
                        int n = n4 * 4 + j;
                        const float* wr = Wout + (size_t)n * HH;
                        float d = 0.f;
                        for (int k = 0; k < HH; k++) d += ax[k] * wr[k];
                        unsigned long long key = amax_key(d + bout[n], n);
                        if (key > best) best = key;
                    }
                }
            }
        }
        #pragma unroll
        for (int off = 16; off; off >>= 1) {
            unsigned long long o = __shfl_xor_sync(0xffffffffu, best, off);
            if (o > best) best = o;
        }
        __syncthreads();
        if (lane == 0 && best) atomicMax(&g_packed[b], best);
        __syncthreads();
    }
}

__global__ void __launch_bounds__(256, 1)
decoder_persist(const float* __restrict__ b_ih, const float* __restrict__ b_hh,
                const float* __restrict__ Wq, const float* __restrict__ bq,
                const float* __restrict__ Wo, const float* __restrict__ bo,
                const float* __restrict__ W_out, const float* __restrict__ b_out,
                float* __restrict__ out) {
    extern __shared__ char smem[];
    unsigned ep = 0;
    for (int t = 0; t < NSTEP; t++) {
        const int pin = t & 1, pout = pin ^ 1;
        lstm_phase(0, pin, t == 0, smem, b_ih, b_hh);
        gridbar(++ep);
        lstm_phase(1, pin, 0, smem, b_ih, b_hh);
        gridbar(++ep);
        gemm512_phase(smem, &g_h[pout][1][0][0], Wq, bq, &g_q[0][0]);
        gridbar(++ep);
        attn_phase(smem);
        gridbar(++ep);
        gemm512_phase(smem, &g_attnT[0][0], Wo, bo, &g_attno[0][0]);
        gridbar(++ep);
        logits_phase(smem, b_out, out, t);
        gridbar(++ep);
        fix_phase(smem, W_out, b_out, out, t);
        gridbar(++ep);
    }
}

extern "C" void kernel_launch(void* const* d_in, const int* in_sizes, int n_in,
                              void* d_out, int out_size) {
    const float* hs     = (const float*)d_in[0];
    const float* hidden = (const float*)d_in[1];
    const float* cell   = (const float*)d_in[2];
    const float* emb    = (const float*)d_in[3];
    const float* W_ih   = (const float*)d_in[4];
    const float* W_hh   = (const float*)d_in[5];
    const float* b_ih   = (const float*)d_in[6];
    const float* b_hh   = (const float*)d_in[7];
    const float* Wq     = (const float*)d_in[8];
    const float* bq     = (const float*)d_in[9];
    const float* Wk     = (const float*)d_in[10];
    const float* bk     = (const float*)d_in[11];
    const float* Wv     = (const float*)d_in[12];
    const float* bv     = (const float*)d_in[13];
    const float* Wo     = (const float*)d_in[14];
    const float* bo     = (const float*)d_in[15];
    const float* W_out  = (const float*)d_in[16];
    const float* b_out  = (const float*)d_in[17];
    float* out = (float*)d_out;

    cudaFuncSetAttribute(decoder_persist, cudaFuncAttributeMaxDynamicSharedMemorySize, SMEM_DYN);

    init_kernel<<<4000, 256>>>(hidden, cell, W_out, emb, W_ih, W_hh, out);

    dim3 kvg(128, 4);
    kv_kernel<<<kvg, 256>>>(hs, Wk, bk, 0);
    kv_kernel<<<kvg, 256>>>(hs, Wv, bv, 1);

    decoder_persist<<<NCTA, 256, SMEM_DYN>>>(b_ih, b_hh, Wq, bq, Wo, bo, W_out, b_out, out);
}

// round 16
// speedup vs baseline: 1.4215x; 1.0727x over previous
#include <cuda_runtime.h>
#include <cuda_bf16.h>
#include <cstdint>

#define SB 32
#define SS 128
#define HH 512
#define VV 32000
#define NSTEP 127
#define NCTA 148

__device__ float g_h[2][2][HH][SB];
__device__ float g_c[2][2][HH][SB];
__device__ __nv_bfloat16 g_hsp[2][2][2][SB][HH];  // [pp][layer][hi/lo][b][dim]
__device__ float g_k[SB][SS][HH];
__device__ float g_v[SB][SS][HH];
__device__ float g_q[SB][HH];
__device__ float g_attnT[HH][SB];
__device__ float g_attno[SB][HH];
__device__ __nv_bfloat16 g_asp[2][SB][HH];        // attno bf16 hi/lo (written by wo)
__device__ unsigned long long g_amax[SB];
__device__ unsigned long long g_packed[SB];
__device__ __nv_bfloat16 g_wh[(size_t)VV * HH];
__device__ __nv_bfloat16 g_wl[(size_t)VV * HH];
__device__ __nv_bfloat16 g_embh[(size_t)VV * HH];
__device__ __nv_bfloat16 g_embl[(size_t)VV * HH];
__device__ __nv_bfloat16 g_lwh[2][4 * HH][2 * HH];
__device__ __nv_bfloat16 g_lwl[2][4 * HH][2 * HH];
__device__ unsigned g_arr[NCTA];
__device__ unsigned g_rel[NCTA];

__device__ __forceinline__ float sigf(float x) { return 1.f / (1.f + expf(-x)); }
__device__ __forceinline__ unsigned long long amax_key(float v, int n) {
    unsigned u = __float_as_uint(v);
    u = (u & 0x80000000u) ? ~u : (u | 0x80000000u);
    return ((unsigned long long)u << 32) | (unsigned)(~(unsigned)n);
}

// two-hop atomic flag-array grid barrier (proven-good)
__device__ __forceinline__ void gridbar(unsigned ep) {
    __syncthreads();
    if (blockIdx.x == 0) {
        if (threadIdx.x == 0) __threadfence();
        __syncthreads();
        if (threadIdx.x > 0 && threadIdx.x < NCTA) {
            while (atomicAdd(&g_arr[threadIdx.x], 0u) < ep) { }
        }
        __syncthreads();
        if (threadIdx.x == 0) __threadfence();
        __syncthreads();
        if (threadIdx.x < NCTA) atomicExch(&g_rel[threadIdx.x], ep);
    } else {
        if (threadIdx.x == 0) {
            __threadfence();
            atomicExch(&g_arr[blockIdx.x], ep);
            while (atomicAdd(&g_rel[blockIdx.x], 0u) < ep) { }
        }
    }
    __syncthreads();
}

__device__ __forceinline__ uint32_t smem_u32(const void* p) {
    uint32_t a;
    asm("{ .reg .u64 t; cvta.to.shared.u64 t, %1; cvt.u32.u64 %0, t; }" : "=r"(a) : "l"(p));
    return a;
}
__device__ __forceinline__ void ldsm_x4(uint32_t* r, uint32_t addr) {
    asm volatile("ldmatrix.sync.aligned.m8n8.x4.shared.b16 {%0,%1,%2,%3}, [%4];"
                 : "=r"(r[0]), "=r"(r[1]), "=r"(r[2]), "=r"(r[3]) : "r"(addr));
}
__device__ __forceinline__ void ldsm_x2(uint32_t* r, uint32_t addr) {
    asm volatile("ldmatrix.sync.aligned.m8n8.x2.shared.b16 {%0,%1}, [%2];"
                 : "=r"(r[0]), "=r"(r[1]) : "r"(addr));
}
__device__ __forceinline__ void mma_bf16(float* c, const uint32_t* a, const uint32_t* b) {
    asm volatile(
        "mma.sync.aligned.m16n8k16.row.col.f32.bf16.bf16.f32 "
        "{%0,%1,%2,%3}, {%4,%5,%6,%7}, {%8,%9}, {%0,%1,%2,%3};"
        : "+f"(c[0]), "+f"(c[1]), "+f"(c[2]), "+f"(c[3])
        : "r"(a[0]), "r"(a[1]), "r"(a[2]), "r"(a[3]), "r"(b[0]), "r"(b[1]));
}
__device__ __forceinline__ void cp16(uint32_t dst, const void* src) {
    asm volatile("cp.async.cg.shared.global [%0], [%1], 16;" :: "r"(dst), "l"(src));
}
__device__ __forceinline__ void cp_commit() { asm volatile("cp.async.commit_group;" ::: "memory"); }
template <int N>
__device__ __forceinline__ void cp_wait() { asm volatile("cp.async.wait_group %0;" :: "n"(N) : "memory"); }

#define ASTRIDE 520
#define L_ABYTES (64 * ASTRIDE * 2)              // 66560
#define L_BBUF   40960                            // 512 rows x 80B
#define SMEM_DYN (L_ABYTES + 3 * L_BBUF + 512)    // 189952

__global__ void init_kernel(const float* __restrict__ hidden, const float* __restrict__ cell,
                            const float* __restrict__ W_out, const float* __restrict__ emb,
                            const float* __restrict__ W_ih, const float* __restrict__ W_hh,
                            float* __restrict__ out) {
    const int idx = blockIdx.x * blockDim.x + threadIdx.x;
    const size_t stride = (size_t)gridDim.x * blockDim.x;
    if (idx < NCTA) { g_arr[idx] = 0; g_rel[idx] = 0; }
    if (idx < 2 * SB * HH) {
        int l = idx >> 14, b = (idx >> 9) & 31, h = idx & 511;
        float hv = hidden[idx];
        g_h[0][l][h][b] = hv;
        g_c[0][l][h][b] = cell[idx];
        __nv_bfloat16 hb = __float2bfloat16(hv);
        g_hsp[0][l][0][b][h] = hb;
        g_hsp[0][l][1][b][h] = __float2bfloat16(hv - __bfloat162float(hb));
    }
    if (idx < SB * VV) {
        int b = idx / VV, v = idx % VV;
        out[(size_t)b * SS * VV + v] = 0.f;
    }
    const size_t nw = (size_t)VV * HH;
    for (size_t i = idx; i < nw; i += stride) {
        float w = W_out[i];
        __nv_bfloat16 h = __float2bfloat16(w);
        g_wh[i] = h;
        g_wl[i] = __float2bfloat16(w - __bfloat162float(h));
        float e = emb[i];
        __nv_bfloat16 eh = __float2bfloat16(e);
        g_embh[i] = eh;
        g_embl[i] = __float2bfloat16(e - __bfloat162float(eh));
    }
    const size_t nlw = (size_t)2 * 4 * HH * 2 * HH;
    for (size_t i = idx; i < nlw; i += stride) {
        int l = (int)(i >> 21);
        int rem = (int)(i & ((1u << 21) - 1));
        int n = rem >> 10, k = rem & 1023;
        float w = (k < HH) ? W_ih[((size_t)l * 4 * HH + n) * HH + k]
                           : W_hh[((size_t)l * 4 * HH + n) * HH + (k - HH)];
        __nv_bfloat16 h = __float2bfloat16(w);
        g_lwh[l][n][k] = h;
        g_lwl[l][n][k] = __float2bfloat16(w - __bfloat162float(h));
    }
}

__global__ void kv_kernel(const float* __restrict__ hs, const float* __restrict__ W,
                          const float* __restrict__ bias, int which) {
    __shared__ float Ash[32][36];
    __shared__ float Wsh[32][132];
    float* dst = which ? &g_v[0][0][0] : &g_k[0][0][0];
    const int r0 = blockIdx.x * 32, n0 = blockIdx.y * 128;
    const int tid = threadIdx.x, lane = tid & 31, grp = tid >> 5;
    float acc[4][4] = {};
    for (int k0 = 0; k0 < HH; k0 += 32) {
        #pragma unroll
        for (int j = 0; j < 4; j++) {
            int m = grp + j * 8, r = r0 + m;
            Ash[lane][m] = hs[(size_t)(r & 127) * (SB * HH) + (r >> 7) * HH + k0 + lane];
        }
        #pragma unroll
        for (int j = 0; j < 16; j++) {
            int nn = grp + j * 8;
            Wsh[lane][nn] = W[(size_t)(n0 + nn) * HH + k0 + lane];
        }
        __syncthreads();
        #pragma unroll
        for (int k = 0; k < 32; k++) {
            float4 a4 = *(const float4*)&Ash[k][grp * 4];
            float4 w4 = *(const float4*)&Wsh[k][lane * 4];
            acc[0][0] += a4.x * w4.x; acc[0][1] += a4.x * w4.y; acc[0][2] += a4.x * w4.z; acc[0][3] += a4.x * w4.w;
            acc[1][0] += a4.y * w4.x; acc[1][1] += a4.y * w4.y; acc[1][2] += a4.y * w4.z; acc[1][3] += a4.y * w4.w;
            acc[2][0] += a4.z * w4.x; acc[2][1] += a4.z * w4.y; acc[2][2] += a4.z * w4.z; acc[2][3] += a4.z * w4.w;
            acc[3][0] += a4.w * w4.x; acc[3][1] += a4.w * w4.y; acc[3][2] += a4.w * w4.z; acc[3][3] += a4.w * w4.w;
        }
        __syncthreads();
    }
    const int nbase = n0 + lane * 4;
    float4 b4 = *(const float4*)&bias[nbase];
    #pragma unroll
    for (int i = 0; i < 4; i++) {
        int r = r0 + grp * 4 + i;
        float4 v;
        v.x = acc[i][0] + b4.x; v.y = acc[i][1] + b4.y;
        v.z = acc[i][2] + b4.z; v.w = acc[i][3] + b4.w;
        *(float4*)&dst[(size_t)r * HH + nbase] = v;
    }
}

// ---- LSTM: 128 tiles x np=4; warps m2 x n2 x k2; bf16 4-product; 4-deep cp.async ----
__device__ void lstm_phase(int layer, int pin, int first, char* smem,
                           const float* __restrict__ b_ih, const float* __restrict__ b_hh) {
    const int tid = threadIdx.x, lane = tid & 31, w = tid >> 5;
    const int pout = pin ^ 1;
    uint32_t abase[4], wbase[4];
    #pragma unroll
    for (int i = 0; i < 4; i++) {
        abase[i] = smem_u32(smem + i * 17408);
        wbase[i] = smem_u32(smem + 69632 + i * 8704);
    }
    float (*Dsh)[16][33] = (float(*)[16][33])(smem + 104448);
    int* tok_s = (int*)(smem + 104448 + 4224);

    for (int tile = blockIdx.x; tile < 128; tile += gridDim.x) {
        const int np0 = tile * 4;
        if (tid < SB) {
            if (first) tok_s[tid] = 0;
            else tok_s[tid] = (int)(~(unsigned)(__ldcg(&g_packed[tid]) & 0xFFFFFFFFull));
        }
        __syncthreads();
        const int arow = tid >> 2, aseg = (tid & 3) * 64;
        const int wrow = tid >> 3, wseg = (tid & 7) * 32;

        auto issue = [&](int c, int buf) {
            const __nv_bfloat16* asrc;
            int s = arow >> 5, b = arow & 31, k0 = c * 128;
            if (k0 < HH) {
                if (layer == 0) asrc = (s ? g_embl : g_embh) + (size_t)tok_s[b] * HH + k0;
                else asrc = &g_hsp[pout][0][s][b][k0];
            } else asrc = &g_hsp[pin][layer][s][b][k0 - HH];
            uint32_t ad = abase[buf] + arow * 272 + aseg;
            const char* ap = (const char*)asrc + aseg;
            #pragma unroll
            for (int j = 0; j < 4; j++) cp16(ad + j * 16, ap + j * 16);
            int ws = wrow >> 4, nl = wrow & 15;
            int n = (nl >> 2) * HH + np0 + (nl & 3);
            const __nv_bfloat16* wsrc = (ws ? &g_lwl[layer][n][0] : &g_lwh[layer][n][0]) + c * 128;
            uint32_t wd = wbase[buf] + wrow * 272 + wseg;
            const char* wp = (const char*)wsrc + wseg;
            cp16(wd, wp);
            cp16(wd + 16, wp + 16);
            cp_commit();
        };

        issue(0, 0); issue(1, 1); issue(2, 2);
        const int om = w & 1, nt = (w >> 1) & 1, kh = w >> 2;
        float acc[4] = {0.f, 0.f, 0.f, 0.f};
        for (int c = 0; c < 8; c++) {
            if (c + 3 < 8) issue(c + 3, (c + 3) & 3);
            if (c <= 4) cp_wait<3>();
            else if (c == 5) cp_wait<2>();
            else if (c == 6) cp_wait<1>();
            else cp_wait<0>();
            __syncthreads();
            const uint32_t au = abase[c & 3], wu = wbase[c & 3];
            #pragma unroll
            for (int kj = 0; kj < 4; kj++) {
                int kt = kh * 4 + kj;
                uint32_t ah[4], al[4], wh[2], wl[2];
                int ar = om * 16 + (lane & 15);
                int kb = kt * 16 + ((lane >> 4) << 3);
                ldsm_x4(ah, au + ar * 272 + kb * 2);
                ldsm_x4(al, au + (ar + 32) * 272 + kb * 2);
                int wr = nt * 8 + (lane & 7);
                int kb2 = kt * 16 + ((lane & 8) ? 8 : 0);
                ldsm_x2(wh, wu + wr * 272 + kb2 * 2);
                ldsm_x2(wl, wu + (wr + 16) * 272 + kb2 * 2);
                mma_bf16(acc, ah, wh);
                mma_bf16(acc, ah, wl);
                mma_bf16(acc, al, wh);
                mma_bf16(acc, al, wl);
            }
            __syncthreads();
        }
        #pragma unroll
        for (int ci = 0; ci < 4; ci++) {
            int b = om * 16 + (lane >> 2) + ((ci >> 1) << 3);
            int nl = nt * 8 + (lane & 3) * 2 + (ci & 1);
            Dsh[kh][nl][b] = acc[ci];
        }
        __syncthreads();
        if (tid < 128) {
            int i = tid >> 5, b = tid & 31, np = np0 + i;
            const size_t bo = (size_t)layer * 4 * HH;
            float s[4];
            #pragma unroll
            for (int g = 0; g < 4; g++)
                s[g] = Dsh[0][g * 4 + i][b] + Dsh[1][g * 4 + i][b]
                     + b_ih[bo + g * HH + np] + b_hh[bo + g * HH + np];
            float cold = __ldcg(&g_c[pin][layer][np][b]);
            float cn = sigf(s[1]) * cold + sigf(s[0]) * tanhf(s[2]);
            float hn = sigf(s[3]) * tanhf(cn);
            __stcg(&g_c[pout][layer][np][b], cn);
            __stcg(&g_h[pout][layer][np][b], hn);
            __nv_bfloat16 hb = __float2bfloat16(hn);
            g_hsp[pout][layer][0][b][np] = hb;
            g_hsp[pout][layer][1][b][np] = __float2bfloat16(hn - __bfloat162float(hb));
        }
        __syncthreads();
    }
}

// ---- generic 512x512 projection: 128 tiles x 4 dims, warp = (row, k-half).
//      split!=0: also store bf16 hi/lo of the result to g_asp (for logits A). ----
__device__ void gemm512_phase(char* smem, const float* __restrict__ src,
                              const float* __restrict__ W, const float* __restrict__ bias,
                              float* __restrict__ dst, int split) {
    float* xs = (float*)smem;                        // [512*32] floats
    float* ws = (float*)(smem + 65536);              // [4][516]
    float* part = (float*)(smem + 65536 + 8256);     // [8][32]
    const int tid = threadIdx.x, lane = tid & 31, w = tid >> 5;
    const uint32_t xu = smem_u32(xs), wu = smem_u32(ws);
    for (int tile = blockIdx.x; tile < 128; tile += gridDim.x) {
        const int d0 = tile * 4;
        #pragma unroll
        for (int j = 0; j < 16; j++) {
            int e = tid + j * 256;
            cp16(xu + e * 16, (const char*)src + e * 16);
        }
        #pragma unroll
        for (int j = 0; j < 2; j++) {
            int e = tid + j * 256;
            int row = e >> 7, seg = e & 127;
            cp16(wu + row * 2064 + seg * 16, W + (size_t)(d0 + row) * HH + seg * 4);
        }
        cp_commit();
        cp_wait<0>();
        __syncthreads();
        const int r = w >> 1, kh = w & 1;
        const float* wr = ws + r * 516 + kh * 256;
        const float* xp = xs + kh * 256 * 32;
        float acc = 0.f;
        #pragma unroll 8
        for (int k = 0; k < 256; k++) acc += xp[k * 32 + lane] * wr[k];
        part[w * 32 + lane] = acc;
        __syncthreads();
        if (tid < 64) {
            int rp = (tid >> 5) * 2, b = tid & 31;
            float v0 = part[(rp * 2) * 32 + b] + part[(rp * 2 + 1) * 32 + b] + bias[d0 + rp];
            float v1 = part[(rp * 2 + 2) * 32 + b] + part[(rp * 2 + 3) * 32 + b] + bias[d0 + rp + 1];
            float2 v2 = make_float2(v0, v1);
            __stcg((float2*)&dst[b * HH + d0 + rp], v2);
            if (split) {
                __nv_bfloat16 h0 = __float2bfloat16(v0), h1 = __float2bfloat16(v1);
                __nv_bfloat16 l0 = __float2bfloat16(v0 - __bfloat162float(h0));
                __nv_bfloat16 l1 = __float2bfloat16(v1 - __bfloat162float(h1));
                unsigned hp = (unsigned)*(unsigned short*)&h0 | ((unsigned)*(unsigned short*)&h1 << 16);
                unsigned lp = (unsigned)*(unsigned short*)&l0 | ((unsigned)*(unsigned short*)&l1 << 16);
                __stcg((unsigned*)&g_asp[0][b][d0 + rp], hp);
                __stcg((unsigned*)&g_asp[1][b][d0 + rp], lp);
            }
        }
        __syncthreads();
    }
}

// ---- attention: 2 half-block units per CTA (proven) ----
__device__ void attn_phase(char* smem) {
    float (*qsm)[64]     = (float(*)[64])smem;
    float (*sc)[128]     = (float(*)[128])(smem + 512);
    float (*red)[8]      = (float(*)[8])(smem + 512 + 1024);
    float (*pav)[2][64]  = (float(*)[2][64])(smem + 512 + 1024 + 64);
    const int tid = threadIdx.x;
    const int h = tid >> 7, wt = tid & 127;
    const int lane = tid & 31, w4 = (tid >> 5) & 3;
    for (int ub = blockIdx.x * 2; ub < 256; ub += gridDim.x * 2) {
        const int u = ub + h;
        const int b = u >> 3, hd = u & 7;
        if (hd == 0 && wt == 0) { __stcg(&g_amax[b], 0ull); __stcg(&g_packed[b], 0ull); }
        if (wt < 64) qsm[h][wt] = __ldcg(&g_q[b][hd * 64 + wt]);
        __syncthreads();
        {
            const float4* kr = (const float4*)&g_k[b][wt][hd * 64];
            const float4* q4 = (const float4*)qsm[h];
            float acc = 0.f;
            #pragma unroll
            for (int d4 = 0; d4 < 16; d4++) {
                float4 kv = kr[d4], qv = q4[d4];
                acc += qv.x * kv.x + qv.y * kv.y + qv.z * kv.z + qv.w * kv.w;
            }
            sc[h][wt] = acc * 0.125f;
        }
        __syncthreads();
        if (wt < 32) {
            float m = fmaxf(fmaxf(sc[h][wt], sc[h][wt + 32]), fmaxf(sc[h][wt + 64], sc[h][wt + 96]));
            #pragma unroll
            for (int off = 16; off; off >>= 1) m = fmaxf(m, __shfl_xor_sync(0xffffffffu, m, off));
            if (lane == 0) red[h][0] = m;
        }
        __syncthreads();
        float mm = red[h][0];
        {
            float e = expf(sc[h][wt] - mm);
            sc[h][wt] = e;
            float s = e;
            #pragma unroll
            for (int off = 16; off; off >>= 1) s += __shfl_xor_sync(0xffffffffu, s, off);
            if (lane == 0) red[h][1 + w4] = s;
        }
        __syncthreads();
        float tot = red[h][1] + red[h][2] + red[h][3] + red[h][4];
        {
            int d = wt & 63, sg = wt >> 6;
            float acc = 0.f;
            #pragma unroll 8
            for (int s5 = 0; s5 < 64; s5++) {
                int s = sg * 64 + s5;
                acc += sc[h][s] * g_v[b][s][hd * 64 + d];
            }
            pav[h][sg][d] = acc;
        }
        __syncthreads();
        if (wt < 64)
            __stcg(&g_attnT[hd * 64 + wt][b], (pav[h][0][wt] + pav[h][1][wt]) / tot);
        __syncthreads();
    }
}

// ---- logits: mma bf16-split, cp.async A-fill + triple-buffered B ----
__device__ void logits_phase(char* smem, const float* __restrict__ bout,
                             float* __restrict__ out, int t) {
    const uint32_t as_u = smem_u32(smem);
    const uint32_t bbase[3] = {smem_u32(smem + L_ABYTES),
                               smem_u32(smem + L_ABYTES + L_BBUF),
                               smem_u32(smem + L_ABYTES + 2 * L_BBUF)};
    unsigned long long* skey = (unsigned long long*)(smem + L_ABYTES + 3 * L_BBUF);
    const int tid = threadIdx.x, lane = tid & 31, w = tid >> 5;

    for (int tile = blockIdx.x; tile < 125; tile += gridDim.x) {
        const int n0 = tile * 256;
        if (tid < 32) skey[tid] = 0ull;

        // A-fill via cp.async from the pre-split g_asp (committed FIRST)
        #pragma unroll
        for (int j = 0; j < 16; j++) {
            int e = j * 256 + tid;
            int row = e >> 6, seg = e & 63;      // 64 rows x 64 segs of 16B
            const __nv_bfloat16* src = (row < 32) ? &g_asp[0][row][0] : &g_asp[1][row - 32][0];
            cp16(as_u + row * (ASTRIDE * 2) + seg * 16, (const char*)src + seg * 16);
        }
        cp_commit();

        auto issueB = [&](int c, int buf) {
            #pragma unroll
            for (int j = 0; j < 8; j++) {
                int e = j * 256 + tid;
                int rr = e >> 2, q = e & 3;
                const __nv_bfloat16* src = (rr & 256) ? g_wl : g_wh;
                cp16(bbase[buf] + rr * 80 + q * 16,
                     src + (size_t)(n0 + (rr & 255)) * HH + c * 32 + q * 8);
            }
            cp_commit();
        };
        issueB(0, 0);
        issueB(1, 1);
        issueB(2, 2);

        float acc[2][4][4] = {};
        for (int kc = 0; kc < 16; kc++) {
            if (kc <= 13) cp_wait<2>();
            else if (kc == 14) cp_wait<1>();
            else cp_wait<0>();
            __syncthreads();
            const uint32_t bu = bbase[kc % 3];
            #pragma unroll
            for (int kk = 0; kk < 32; kk += 16) {
                const int ka = kc * 32 + kk;
                uint32_t ah[2][4], al[2][4], bh[4][2], bl[4][2];
                #pragma unroll
                for (int mt = 0; mt < 2; mt++) {
                    int r = mt * 16 + (lane & 15);
                    int k = ka + (((lane >> 4) & 1) << 3);
                    ldsm_x4(ah[mt], as_u + (r * ASTRIDE + k) * 2);
                    ldsm_x4(al[mt], as_u + ((32 + r) * ASTRIDE + k) * 2);
                }
                #pragma unroll
                for (int nt = 0; nt < 4; nt++) {
                    int nrow = w * 32 + nt * 8 + (lane & 7);
                    int k = kk + ((lane & 8) ? 8 : 0);
                    ldsm_x2(bh[nt], bu + nrow * 80 + k * 2);
                    ldsm_x2(bl[nt], bu + (256 + nrow) * 80 + k * 2);
                }
                #pragma unroll
                for (int mt = 0; mt < 2; mt++)
                    #pragma unroll
                    for (int nt = 0; nt < 4; nt++) {
                        mma_bf16(acc[mt][nt], ah[mt], bh[nt]);
                        mma_bf16(acc[mt][nt], ah[mt], bl[nt]);
                        mma_bf16(acc[mt][nt], al[mt], bh[nt]);
                    }
            }
            __syncthreads();
            if (kc + 3 < 16) issueB(kc + 3, (kc + 3) % 3);
        }

        unsigned long long lkey[2][2] = {{0ull, 0ull}, {0ull, 0ull}};
        #pragma unroll
        for (int mt = 0; mt < 2; mt++)
            #pragma unroll
            for (int nt = 0; nt < 4; nt++) {
                int n = n0 + w * 32 + nt * 8 + (lane & 3) * 2;
                float2 bias = *(const float2*)&bout[n];
                #pragma unroll
                for (int h = 0; h < 2; h++) {
                    int b = mt * 16 + (lane >> 2) + h * 8;
                    float2 v;
                    v.x = acc[mt][nt][h * 2] + bias.x;
                    v.y = acc[mt][nt][h * 2 + 1] + bias.y;
                    *(float2*)&out[((size_t)b * SS + t + 1) * VV + n] = v;
                    unsigned long long k1 = amax_key(v.x, n);
                    unsigned long long k2 = amax_key(v.y, n + 1);
                    if (k2 > k1) k1 = k2;
                    if (k1 > lkey[mt][h]) lkey[mt][h] = k1;
                }
            }
        #pragma unroll
        for (int mt = 0; mt < 2; mt++)
            #pragma unroll
            for (int h = 0; h < 2; h++) {
                unsigned long long kk = lkey[mt][h];
                unsigned long long o = __shfl_xor_sync(0xffffffffu, kk, 1); if (o > kk) kk = o;
                o = __shfl_xor_sync(0xffffffffu, kk, 2); if (o > kk) kk = o;
                if ((lane & 3) == 0) atomicMax(&skey[mt * 16 + (lane >> 2) + h * 8], kk);
            }
        __syncthreads();
        if (tid < 32 && skey[tid]) atomicMax(&g_amax[tid], skey[tid]);
        __syncthreads();
    }
}

// ---- fix: 128 (b, quarter) units; fp32-exact argmax among candidates ----
__device__ void fix_phase(char* smem, const float* __restrict__ Wout,
                          const float* __restrict__ bout,
                          const float* __restrict__ out, int t) {
    float* ax = (float*)smem;
    const int tid = threadIdx.x, lane = tid & 31;
    for (int u = blockIdx.x; u < 128; u += gridDim.x) {
        const int b = u >> 2, qtr = u & 3;
        for (int d = tid; d < HH; d += 256) ax[d] = __ldcg(&g_attno[b][d]);
        __syncthreads();
        unsigned long long ak = __ldcg(&g_amax[b]);
        unsigned ue = (unsigned)(ak >> 32);
        unsigned uv = (ue & 0x80000000u) ? (ue & 0x7fffffffu) : ~ue;
        const float thr = __uint_as_float(uv) - 1e-2f;
        const float* row = out + ((size_t)b * SS + t + 1) * VV;
        unsigned long long best = 0ull;
        for (int n4 = qtr * 2000 + tid; n4 < (qtr + 1) * 2000; n4 += 256) {
            float4 v = __ldcg((const float4*)&row[n4 * 4]);
            float mv = fmaxf(fmaxf(v.x, v.y), fmaxf(v.z, v.w));
            if (mv >= thr) {
                float vv[4] = {v.x, v.y, v.z, v.w};
                #pragma unroll
                for (int j = 0; j < 4; j++) {
                    if (vv[j] >= thr) {
                        int n = n4 * 4 + j;
                        const float* wr = Wout + (size_t)n * HH;
                        float d = 0.f;
                        for (int k = 0; k < HH; k++) d += ax[k] * wr[k];
                        unsigned long long key = amax_key(d + bout[n], n);
                        if (key > best) best = key;
                    }
                }
            }
        }
        #pragma unroll
        for (int off = 16; off; off >>= 1) {
            unsigned long long o = __shfl_xor_sync(0xffffffffu, best, off);
            if (o > best) best = o;
        }
        __syncthreads();
        if (lane == 0 && best) atomicMax(&g_packed[b], best);
        __syncthreads();
    }
}

__global__ void __launch_bounds__(256, 1)
decoder_persist(const float* __restrict__ b_ih, const float* __restrict__ b_hh,
                const float* __restrict__ Wq, const float* __restrict__ bq,
                const float* __restrict__ Wo, const float* __restrict__ bo,
                const float* __restrict__ W_out, const float* __restrict__ b_out,
                float* __restrict__ out) {
    extern __shared__ char smem[];
    unsigned ep = 0;
    for (int t = 0; t < NSTEP; t++) {
        const int pin = t & 1, pout = pin ^ 1;
        lstm_phase(0, pin, t == 0, smem, b_ih, b_hh);
        gridbar(++ep);
        lstm_phase(1, pin, 0, smem, b_ih, b_hh);
        gridbar(++ep);
        gemm512_phase(smem, &g_h[pout][1][0][0], Wq, bq, &g_q[0][0], 0);
        gridbar(++ep);
        attn_phase(smem);
        gridbar(++ep);
        gemm512_phase(smem, &g_attnT[0][0], Wo, bo, &g_attno[0][0], 1);
        gridbar(++ep);
        logits_phase(smem, b_out, out, t);
        if (t < NSTEP - 1) {
            gridbar(++ep);
            fix_phase(smem, W_out, b_out, out, t);
            gridbar(++ep);
        }
    }
}

extern "C" void kernel_launch(void* const* d_in, const int* in_sizes, int n_in,
                              void* d_out, int out_size) {
    const float* hs     = (const float*)d_in[0];
    const float* hidden = (const float*)d_in[1];
    const float* cell   = (const float*)d_in[2];
    const float* emb    = (const float*)d_in[3];
    const float* W_ih   = (const float*)d_in[4];
    const float* W_hh   = (const float*)d_in[5];
    const float* b_ih   = (const float*)d_in[6];
    const float* b_hh   = (const float*)d_in[7];
    const float* Wq     = (const float*)d_in[8];
    const float* bq     = (const float*)d_in[9];
    const float* Wk     = (const float*)d_in[10];
    const float* bk     = (const float*)d_in[11];
    const float* Wv     = (const float*)d_in[12];
    const float* bv     = (const float*)d_in[13];
    const float* Wo     = (const float*)d_in[14];
    const float* bo     = (const float*)d_in[15];
    const float* W_out  = (const float*)d_in[16];
    const float* b_out  = (const float*)d_in[17];
    float* out = (float*)d_out;

    cudaFuncSetAttribute(decoder_persist, cudaFuncAttributeMaxDynamicSharedMemorySize, SMEM_DYN);

    init_kernel<<<4000, 256>>>(hidden, cell, W_out, emb, W_ih, W_hh, out);

    dim3 kvg(128, 4);
    kv_kernel<<<kvg, 256>>>(hs, Wk, bk, 0);
    kv_kernel<<<kvg, 256>>>(hs, Wv, bv, 1);

    decoder_persist<<<NCTA, 256, SMEM_DYN>>>(b_ih, b_hh, Wq, bq, Wo, bo, W_out, b_out, out);
}

// round 17
// speedup vs baseline: 1.5334x; 1.0787x over previous
#include <cuda_runtime.h>
#include <cuda_bf16.h>
#include <cstdint>

#define SB 32
#define SS 128
#define HH 512
#define VV 32000
#define NSTEP 127
#define NCTA 148

__device__ float g_h[2][2][HH][SB];
__device__ float g_c[2][2][HH][SB];
__device__ __nv_bfloat16 g_hsp[2][2][2][SB][HH];  // [pp][layer][hi/lo][b][dim]
__device__ float g_k[SB][SS][HH];
__device__ float g_v[SB][SS][HH];
__device__ float g_q[SB][HH];
__device__ float g_attnT[HH][SB];
__device__ float g_attno[SB][HH];
__device__ __nv_bfloat16 g_asp[2][SB][HH];        // attno bf16 hi/lo (written by wo)
__device__ unsigned long long g_amax[SB];
__device__ unsigned long long g_packed[SB];
__device__ __nv_bfloat16 g_wh[(size_t)VV * HH];
__device__ __nv_bfloat16 g_wl[(size_t)VV * HH];
__device__ __nv_bfloat16 g_embh[(size_t)VV * HH];
__device__ __nv_bfloat16 g_embl[(size_t)VV * HH];
__device__ __nv_bfloat16 g_lwh[2][4 * HH][2 * HH];
__device__ __nv_bfloat16 g_lwl[2][4 * HH][2 * HH];
__device__ unsigned g_arr[NCTA];
__device__ unsigned g_rel[NCTA];

__device__ __forceinline__ float sigf(float x) { return 1.f / (1.f + expf(-x)); }
__device__ __forceinline__ unsigned long long amax_key(float v, int n) {
    unsigned u = __float_as_uint(v);
    u = (u & 0x80000000u) ? ~u : (u | 0x80000000u);
    return ((unsigned long long)u << 32) | (unsigned)(~(unsigned)n);
}

// two-hop atomic flag-array grid barrier (proven-good)
__device__ __forceinline__ void gridbar(unsigned ep) {
    __syncthreads();
    if (blockIdx.x == 0) {
        if (threadIdx.x == 0) __threadfence();
        __syncthreads();
        if (threadIdx.x > 0 && threadIdx.x < NCTA) {
            while (atomicAdd(&g_arr[threadIdx.x], 0u) < ep) { }
        }
        __syncthreads();
        if (threadIdx.x == 0) __threadfence();
        __syncthreads();
        if (threadIdx.x < NCTA) atomicExch(&g_rel[threadIdx.x], ep);
    } else {
        if (threadIdx.x == 0) {
            __threadfence();
            atomicExch(&g_arr[blockIdx.x], ep);
            while (atomicAdd(&g_rel[blockIdx.x], 0u) < ep) { }
        }
    }
    __syncthreads();
}

__device__ __forceinline__ uint32_t smem_u32(const void* p) {
    uint32_t a;
    asm("{ .reg .u64 t; cvta.to.shared.u64 t, %1; cvt.u32.u64 %0, t; }" : "=r"(a) : "l"(p));
    return a;
}
__device__ __forceinline__ void ldsm_x4(uint32_t* r, uint32_t addr) {
    asm volatile("ldmatrix.sync.aligned.m8n8.x4.shared.b16 {%0,%1,%2,%3}, [%4];"
                 : "=r"(r[0]), "=r"(r[1]), "=r"(r[2]), "=r"(r[3]) : "r"(addr));
}
__device__ __forceinline__ void ldsm_x2(uint32_t* r, uint32_t addr) {
    asm volatile("ldmatrix.sync.aligned.m8n8.x2.shared.b16 {%0,%1}, [%2];"
                 : "=r"(r[0]), "=r"(r[1]) : "r"(addr));
}
__device__ __forceinline__ void mma_bf16(float* c, const uint32_t* a, const uint32_t* b) {
    asm volatile(
        "mma.sync.aligned.m16n8k16.row.col.f32.bf16.bf16.f32 "
        "{%0,%1,%2,%3}, {%4,%5,%6,%7}, {%8,%9}, {%0,%1,%2,%3};"
        : "+f"(c[0]), "+f"(c[1]), "+f"(c[2]), "+f"(c[3])
        : "r"(a[0]), "r"(a[1]), "r"(a[2]), "r"(a[3]), "r"(b[0]), "r"(b[1]));
}
__device__ __forceinline__ void cp16(uint32_t dst, const void* src) {
    asm volatile("cp.async.cg.shared.global [%0], [%1], 16;" :: "r"(dst), "l"(src));
}
__device__ __forceinline__ void cp_commit() { asm volatile("cp.async.commit_group;" ::: "memory"); }
template <int N>
__device__ __forceinline__ void cp_wait() { asm volatile("cp.async.wait_group %0;" :: "n"(N) : "memory"); }

#define ASTRIDE 520
#define L_ABYTES (64 * ASTRIDE * 2)              // 66560
#define L_BBUF   40960                            // 512 rows x 80B
#define SMEM_DYN (L_ABYTES + 3 * L_BBUF + 512)    // 189952

__global__ void init_kernel(const float* __restrict__ hidden, const float* __restrict__ cell,
                            const float* __restrict__ W_out, const float* __restrict__ emb,
                            const float* __restrict__ W_ih, const float* __restrict__ W_hh,
                            float* __restrict__ out) {
    const int idx = blockIdx.x * blockDim.x + threadIdx.x;
    const size_t stride = (size_t)gridDim.x * blockDim.x;
    if (idx < NCTA) { g_arr[idx] = 0; g_rel[idx] = 0; }
    if (idx < 2 * SB * HH) {
        int l = idx >> 14, b = (idx >> 9) & 31, h = idx & 511;
        float hv = hidden[idx];
        g_h[0][l][h][b] = hv;
        g_c[0][l][h][b] = cell[idx];
        __nv_bfloat16 hb = __float2bfloat16(hv);
        g_hsp[0][l][0][b][h] = hb;
        g_hsp[0][l][1][b][h] = __float2bfloat16(hv - __bfloat162float(hb));
    }
    if (idx < SB * VV) {
        int b = idx / VV, v = idx % VV;
        out[(size_t)b * SS * VV + v] = 0.f;
    }
    const size_t nw = (size_t)VV * HH;
    for (size_t i = idx; i < nw; i += stride) {
        float w = W_out[i];
        __nv_bfloat16 h = __float2bfloat16(w);
        g_wh[i] = h;
        g_wl[i] = __float2bfloat16(w - __bfloat162float(h));
        float e = emb[i];
        __nv_bfloat16 eh = __float2bfloat16(e);
        g_embh[i] = eh;
        g_embl[i] = __float2bfloat16(e - __bfloat162float(eh));
    }
    const size_t nlw = (size_t)2 * 4 * HH * 2 * HH;
    for (size_t i = idx; i < nlw; i += stride) {
        int l = (int)(i >> 21);
        int rem = (int)(i & ((1u << 21) - 1));
        int n = rem >> 10, k = rem & 1023;
        float w = (k < HH) ? W_ih[((size_t)l * 4 * HH + n) * HH + k]
                           : W_hh[((size_t)l * 4 * HH + n) * HH + (k - HH)];
        __nv_bfloat16 h = __float2bfloat16(w);
        g_lwh[l][n][k] = h;
        g_lwl[l][n][k] = __float2bfloat16(w - __bfloat162float(h));
    }
}

__global__ void kv_kernel(const float* __restrict__ hs, const float* __restrict__ W,
                          const float* __restrict__ bias, int which) {
    __shared__ float Ash[32][36];
    __shared__ float Wsh[32][132];
    float* dst = which ? &g_v[0][0][0] : &g_k[0][0][0];
    const int r0 = blockIdx.x * 32, n0 = blockIdx.y * 128;
    const int tid = threadIdx.x, lane = tid & 31, grp = tid >> 5;
    float acc[4][4] = {};
    for (int k0 = 0; k0 < HH; k0 += 32) {
        #pragma unroll
        for (int j = 0; j < 4; j++) {
            int m = grp + j * 8, r = r0 + m;
            Ash[lane][m] = hs[(size_t)(r & 127) * (SB * HH) + (r >> 7) * HH + k0 + lane];
        }
        #pragma unroll
        for (int j = 0; j < 16; j++) {
            int nn = grp + j * 8;
            Wsh[lane][nn] = W[(size_t)(n0 + nn) * HH + k0 + lane];
        }
        __syncthreads();
        #pragma unroll
        for (int k = 0; k < 32; k++) {
            float4 a4 = *(const float4*)&Ash[k][grp * 4];
            float4 w4 = *(const float4*)&Wsh[k][lane * 4];
            acc[0][0] += a4.x * w4.x; acc[0][1] += a4.x * w4.y; acc[0][2] += a4.x * w4.z; acc[0][3] += a4.x * w4.w;
            acc[1][0] += a4.y * w4.x; acc[1][1] += a4.y * w4.y; acc[1][2] += a4.y * w4.z; acc[1][3] += a4.y * w4.w;
            acc[2][0] += a4.z * w4.x; acc[2][1] += a4.z * w4.y; acc[2][2] += a4.z * w4.z; acc[2][3] += a4.z * w4.w;
            acc[3][0] += a4.w * w4.x; acc[3][1] += a4.w * w4.y; acc[3][2] += a4.w * w4.z; acc[3][3] += a4.w * w4.w;
        }
        __syncthreads();
    }
    const int nbase = n0 + lane * 4;
    float4 b4 = *(const float4*)&bias[nbase];
    #pragma unroll
    for (int i = 0; i < 4; i++) {
        int r = r0 + grp * 4 + i;
        float4 v;
        v.x = acc[i][0] + b4.x; v.y = acc[i][1] + b4.y;
        v.z = acc[i][2] + b4.z; v.w = acc[i][3] + b4.w;
        *(float4*)&dst[(size_t)r * HH + nbase] = v;
    }
}

// ---- LSTM: 128 tiles x np=4; 16 warps = m2 x n2 x k4; 4-deep cp.async ----
__device__ void lstm_phase(int layer, int pin, int first, char* smem,
                           const float* __restrict__ b_ih, const float* __restrict__ b_hh) {
    const int tid = threadIdx.x, lane = tid & 31, w = tid >> 5;
    const int pout = pin ^ 1;
    uint32_t abase[4], wbase[4];
    #pragma unroll
    for (int i = 0; i < 4; i++) {
        abase[i] = smem_u32(smem + i * 17408);
        wbase[i] = smem_u32(smem + 69632 + i * 8704);
    }
    float (*Dsh)[16][33] = (float(*)[16][33])(smem + 104448);   // [4][16][33]
    int* tok_s = (int*)(smem + 104448 + 8448);

    for (int tile = blockIdx.x; tile < 128; tile += gridDim.x) {
        const int np0 = tile * 4;
        if (tid < SB) {
            if (first) tok_s[tid] = 0;
            else tok_s[tid] = (int)(~(unsigned)(__ldcg(&g_packed[tid]) & 0xFFFFFFFFull));
        }
        __syncthreads();
        const int arow = tid >> 3, aseg = (tid & 7) * 32;
        const int wrow = tid >> 4, wseg = (tid & 15) * 16;

        auto issue = [&](int c, int buf) {
            const __nv_bfloat16* asrc;
            int s = arow >> 5, b = arow & 31, k0 = c * 128;
            if (k0 < HH) {
                if (layer == 0) asrc = (s ? g_embl : g_embh) + (size_t)tok_s[b] * HH + k0;
                else asrc = &g_hsp[pout][0][s][b][k0];
            } else asrc = &g_hsp[pin][layer][s][b][k0 - HH];
            uint32_t ad = abase[buf] + arow * 272 + aseg;
            const char* ap = (const char*)asrc + aseg;
            cp16(ad, ap);
            cp16(ad + 16, ap + 16);
            int ws = wrow >> 4, nl = wrow & 15;
            int n = (nl >> 2) * HH + np0 + (nl & 3);
            const __nv_bfloat16* wsrc = (ws ? &g_lwl[layer][n][0] : &g_lwh[layer][n][0]) + c * 128;
            cp16(wbase[buf] + wrow * 272 + wseg, (const char*)wsrc + wseg);
            cp_commit();
        };

        issue(0, 0); issue(1, 1); issue(2, 2);
        const int om = w & 1, nt = (w >> 1) & 1, kh = w >> 2;  // kh 0..3
        float acc[4] = {0.f, 0.f, 0.f, 0.f};
        for (int c = 0; c < 8; c++) {
            if (c + 3 < 8) issue(c + 3, (c + 3) & 3);
            if (c <= 4) cp_wait<3>();
            else if (c == 5) cp_wait<2>();
            else if (c == 6) cp_wait<1>();
            else cp_wait<0>();
            __syncthreads();
            const uint32_t au = abase[c & 3], wu = wbase[c & 3];
            #pragma unroll
            for (int kj = 0; kj < 2; kj++) {
                int kt = kh * 2 + kj;
                uint32_t ah[4], al[4], wh[2], wl[2];
                int ar = om * 16 + (lane & 15);
                int kb = kt * 16 + ((lane >> 4) << 3);
                ldsm_x4(ah, au + ar * 272 + kb * 2);
                ldsm_x4(al, au + (ar + 32) * 272 + kb * 2);
                int wr = nt * 8 + (lane & 7);
                int kb2 = kt * 16 + ((lane & 8) ? 8 : 0);
                ldsm_x2(wh, wu + wr * 272 + kb2 * 2);
                ldsm_x2(wl, wu + (wr + 16) * 272 + kb2 * 2);
                mma_bf16(acc, ah, wh);
                mma_bf16(acc, ah, wl);
                mma_bf16(acc, al, wh);
                mma_bf16(acc, al, wl);
            }
            __syncthreads();
        }
        #pragma unroll
        for (int ci = 0; ci < 4; ci++) {
            int b = om * 16 + (lane >> 2) + ((ci >> 1) << 3);
            int nl = nt * 8 + (lane & 3) * 2 + (ci & 1);
            Dsh[kh][nl][b] = acc[ci];
        }
        __syncthreads();
        if (tid < 128) {
            int i = tid >> 5, b = tid & 31, np = np0 + i;
            const size_t bo = (size_t)layer * 4 * HH;
            float s[4];
            #pragma unroll
            for (int g = 0; g < 4; g++)
                s[g] = (Dsh[0][g * 4 + i][b] + Dsh[1][g * 4 + i][b])
                     + (Dsh[2][g * 4 + i][b] + Dsh[3][g * 4 + i][b])
                     + b_ih[bo + g * HH + np] + b_hh[bo + g * HH + np];
            float cold = __ldcg(&g_c[pin][layer][np][b]);
            float cn = sigf(s[1]) * cold + sigf(s[0]) * tanhf(s[2]);
            float hn = sigf(s[3]) * tanhf(cn);
            __stcg(&g_c[pout][layer][np][b], cn);
            __stcg(&g_h[pout][layer][np][b], hn);
            __nv_bfloat16 hb = __float2bfloat16(hn);
            g_hsp[pout][layer][0][b][np] = hb;
            g_hsp[pout][layer][1][b][np] = __float2bfloat16(hn - __bfloat162float(hb));
        }
        __syncthreads();
    }
}

// ---- gemm512: 128 tiles x 4 dims; 16 warps = (row4, k-quarter4) ----
__device__ void gemm512_phase(char* smem, const float* __restrict__ src,
                              const float* __restrict__ W, const float* __restrict__ bias,
                              float* __restrict__ dst, int split) {
    float* xs = (float*)smem;                        // [512*32]
    float* ws = (float*)(smem + 65536);              // [4][516]
    float* part = (float*)(smem + 65536 + 8256);     // [16][32]
    const int tid = threadIdx.x, lane = tid & 31, w = tid >> 5;
    const uint32_t xu = smem_u32(xs), wu = smem_u32(ws);
    for (int tile = blockIdx.x; tile < 128; tile += gridDim.x) {
        const int d0 = tile * 4;
        #pragma unroll
        for (int j = 0; j < 8; j++) {
            int e = tid + j * 512;
            cp16(xu + e * 16, (const char*)src + e * 16);
        }
        {
            int row = tid >> 7, seg = tid & 127;
            cp16(wu + row * 2064 + seg * 16, W + (size_t)(d0 + row) * HH + seg * 4);
        }
        cp_commit();
        cp_wait<0>();
        __syncthreads();
        const int r = w >> 2, kq = w & 3;
        const float* wr = ws + r * 516 + kq * 128;
        const float* xp = xs + kq * 128 * 32;
        float acc = 0.f;
        #pragma unroll 8
        for (int k = 0; k < 128; k++) acc += xp[k * 32 + lane] * wr[k];
        part[w * 32 + lane] = acc;
        __syncthreads();
        if (tid < 64) {
            int rp = (tid >> 5) * 2, b = tid & 31;
            float v0 = (part[(rp * 4) * 32 + b] + part[(rp * 4 + 1) * 32 + b])
                     + (part[(rp * 4 + 2) * 32 + b] + part[(rp * 4 + 3) * 32 + b]) + bias[d0 + rp];
            float v1 = (part[((rp + 1) * 4) * 32 + b] + part[((rp + 1) * 4 + 1) * 32 + b])
                     + (part[((rp + 1) * 4 + 2) * 32 + b] + part[((rp + 1) * 4 + 3) * 32 + b]) + bias[d0 + rp + 1];
            float2 v2 = make_float2(v0, v1);
            __stcg((float2*)&dst[b * HH + d0 + rp], v2);
            if (split) {
                __nv_bfloat16 h0 = __float2bfloat16(v0), h1 = __float2bfloat16(v1);
                __nv_bfloat16 l0 = __float2bfloat16(v0 - __bfloat162float(h0));
                __nv_bfloat16 l1 = __float2bfloat16(v1 - __bfloat162float(h1));
                unsigned hp = (unsigned)*(unsigned short*)&h0 | ((unsigned)*(unsigned short*)&h1 << 16);
                unsigned lp = (unsigned)*(unsigned short*)&l0 | ((unsigned)*(unsigned short*)&l1 << 16);
                __stcg((unsigned*)&g_asp[0][b][d0 + rp], hp);
                __stcg((unsigned*)&g_asp[1][b][d0 + rp], lp);
            }
        }
        __syncthreads();
    }
}

// ---- attention: 4 quarter-block units per CTA (128 thr each) ----
__device__ void attn_phase(char* smem) {
    float (*qsm)[64]     = (float(*)[64])smem;                           // [4][64]
    float (*sc)[128]     = (float(*)[128])(smem + 1024);                 // [4][128]
    float (*red)[8]      = (float(*)[8])(smem + 1024 + 2048);            // [4][8]
    float (*pav)[2][64]  = (float(*)[2][64])(smem + 1024 + 2048 + 128);  // [4][2][64]
    const int tid = threadIdx.x;
    const int h = tid >> 7, wt = tid & 127;
    const int lane = tid & 31, w4 = (tid >> 5) & 3;
    for (int ub = blockIdx.x * 4; ub < 256; ub += gridDim.x * 4) {
        const int u = ub + h;              // 256 % 4 == 0 -> uniform trip count
        const int b = u >> 3, hd = u & 7;
        if (hd == 0 && wt == 0) { __stcg(&g_amax[b], 0ull); __stcg(&g_packed[b], 0ull); }
        if (wt < 64) qsm[h][wt] = __ldcg(&g_q[b][hd * 64 + wt]);
        __syncthreads();
        {
            const float4* kr = (const float4*)&g_k[b][wt][hd * 64];
            const float4* q4 = (const float4*)qsm[h];
            float acc = 0.f;
            #pragma unroll
            for (int d4 = 0; d4 < 16; d4++) {
                float4 kv = kr[d4], qv = q4[d4];
                acc += qv.x * kv.x + qv.y * kv.y + qv.z * kv.z + qv.w * kv.w;
            }
            sc[h][wt] = acc * 0.125f;
        }
        __syncthreads();
        if (wt < 32) {
            float m = fmaxf(fmaxf(sc[h][wt], sc[h][wt + 32]), fmaxf(sc[h][wt + 64], sc[h][wt + 96]));
            #pragma unroll
            for (int off = 16; off; off >>= 1) m = fmaxf(m, __shfl_xor_sync(0xffffffffu, m, off));
            if (lane == 0) red[h][0] = m;
        }
        __syncthreads();
        float mm = red[h][0];
        {
            float e = expf(sc[h][wt] - mm);
            sc[h][wt] = e;
            float s = e;
            #pragma unroll
            for (int off = 16; off; off >>= 1) s += __shfl_xor_sync(0xffffffffu, s, off);
            if (lane == 0) red[h][1 + w4] = s;
        }
        __syncthreads();
        float tot = red[h][1] + red[h][2] + red[h][3] + red[h][4];
        {
            int d = wt & 63, sg = wt >> 6;
            float acc = 0.f;
            #pragma unroll 8
            for (int s5 = 0; s5 < 64; s5++) {
                int s = sg * 64 + s5;
                acc += sc[h][s] * g_v[b][s][hd * 64 + d];
            }
            pav[h][sg][d] = acc;
        }
        __syncthreads();
        if (wt < 64)
            __stcg(&g_attnT[hd * 64 + wt][b], (pav[h][0][wt] + pav[h][1][wt]) / tot);
        __syncthreads();
    }
}

// ---- logits: mma bf16-split, cp.async A + triple-buffered B; 16 warps x 16 cols ----
__device__ void logits_phase(char* smem, const float* __restrict__ bout,
                             float* __restrict__ out, int t) {
    const uint32_t as_u = smem_u32(smem);
    const uint32_t bbase[3] = {smem_u32(smem + L_ABYTES),
                               smem_u32(smem + L_ABYTES + L_BBUF),
                               smem_u32(smem + L_ABYTES + 2 * L_BBUF)};
    unsigned long long* skey = (unsigned long long*)(smem + L_ABYTES + 3 * L_BBUF);
    const int tid = threadIdx.x, lane = tid & 31, w = tid >> 5;

    for (int tile = blockIdx.x; tile < 125; tile += gridDim.x) {
        const int n0 = tile * 256;
        if (tid < 32) skey[tid] = 0ull;

        #pragma unroll
        for (int j = 0; j < 8; j++) {
            int e = j * 512 + tid;
            int row = e >> 6, seg = e & 63;
            const __nv_bfloat16* src = (row < 32) ? &g_asp[0][row][0] : &g_asp[1][row - 32][0];
            cp16(as_u + row * (ASTRIDE * 2) + seg * 16, (const char*)src + seg * 16);
        }
        cp_commit();

        auto issueB = [&](int c, int buf) {
            #pragma unroll
            for (int j = 0; j < 4; j++) {
                int e = j * 512 + tid;
                int rr = e >> 2, q = e & 3;
                const __nv_bfloat16* src = (rr & 256) ? g_wl : g_wh;
                cp16(bbase[buf] + rr * 80 + q * 16,
                     src + (size_t)(n0 + (rr & 255)) * HH + c * 32 + q * 8);
            }
            cp_commit();
        };
        issueB(0, 0);
        issueB(1, 1);
        issueB(2, 2);

        float acc[2][2][4] = {};
        for (int kc = 0; kc < 16; kc++) {
            if (kc <= 13) cp_wait<2>();
            else if (kc == 14) cp_wait<1>();
            else cp_wait<0>();
            __syncthreads();
            const uint32_t bu = bbase[kc % 3];
            #pragma unroll
            for (int kk = 0; kk < 32; kk += 16) {
                const int ka = kc * 32 + kk;
                uint32_t ah[2][4], al[2][4], bh[2][2], bl[2][2];
                #pragma unroll
                for (int mt = 0; mt < 2; mt++) {
                    int r = mt * 16 + (lane & 15);
                    int k = ka + (((lane >> 4) & 1) << 3);
                    ldsm_x4(ah[mt], as_u + (r * ASTRIDE + k) * 2);
                    ldsm_x4(al[mt], as_u + ((32 + r) * ASTRIDE + k) * 2);
                }
                #pragma unroll
                for (int nt = 0; nt < 2; nt++) {
                    int nrow = w * 16 + nt * 8 + (lane & 7);
                    int k = kk + ((lane & 8) ? 8 : 0);
                    ldsm_x2(bh[nt], bu + nrow * 80 + k * 2);
                    ldsm_x2(bl[nt], bu + (256 + nrow) * 80 + k * 2);
                }
                #pragma unroll
                for (int mt = 0; mt < 2; mt++)
                    #pragma unroll
                    for (int nt = 0; nt < 2; nt++) {
                        mma_bf16(acc[mt][nt], ah[mt], bh[nt]);
                        mma_bf16(acc[mt][nt], ah[mt], bl[nt]);
                        mma_bf16(acc[mt][nt], al[mt], bh[nt]);
                    }
            }
            __syncthreads();
            if (kc + 3 < 16) issueB(kc + 3, (kc + 3) % 3);
        }

        unsigned long long lkey[2][2] = {{0ull, 0ull}, {0ull, 0ull}};
        #pragma unroll
        for (int mt = 0; mt < 2; mt++)
            #pragma unroll
            for (int nt = 0; nt < 2; nt++) {
                int n = n0 + w * 16 + nt * 8 + (lane & 3) * 2;
                float2 bias = *(const float2*)&bout[n];
                #pragma unroll
                for (int h = 0; h < 2; h++) {
                    int b = mt * 16 + (lane >> 2) + h * 8;
                    float2 v;
                    v.x = acc[mt][nt][h * 2] + bias.x;
                    v.y = acc[mt][nt][h * 2 + 1] + bias.y;
                    *(float2*)&out[((size_t)b * SS + t + 1) * VV + n] = v;
                    unsigned long long k1 = amax_key(v.x, n);
                    unsigned long long k2 = amax_key(v.y, n + 1);
                    if (k2 > k1) k1 = k2;
                    if (k1 > lkey[mt][h]) lkey[mt][h] = k1;
                }
            }
        #pragma unroll
        for (int mt = 0; mt < 2; mt++)
            #pragma unroll
            for (int h = 0; h < 2; h++) {
                unsigned long long kk = lkey[mt][h];
                unsigned long long o = __shfl_xor_sync(0xffffffffu, kk, 1); if (o > kk) kk = o;
                o = __shfl_xor_sync(0xffffffffu, kk, 2); if (o > kk) kk = o;
                if ((lane & 3) == 0) atomicMax(&skey[mt * 16 + (lane >> 2) + h * 8], kk);
            }
        __syncthreads();
        if (tid < 32 && skey[tid]) atomicMax(&g_amax[tid], skey[tid]);
        __syncthreads();
    }
}

// ---- fix: 128 (b, quarter) units; fp32-exact argmax among candidates ----
__device__ void fix_phase(char* smem, const float* __restrict__ Wout,
                          const float* __restrict__ bout,
                          const float* __restrict__ out, int t) {
    float* ax = (float*)smem;
    const int tid = threadIdx.x, lane = tid & 31;
    for (int u = blockIdx.x; u < 128; u += gridDim.x) {
        const int b = u >> 2, qtr = u & 3;
        if (tid < HH) ax[tid] = __ldcg(&g_attno[b][tid]);
        __syncthreads();
        unsigned long long ak = __ldcg(&g_amax[b]);
        unsigned ue = (unsigned)(ak >> 32);
        unsigned uv = (ue & 0x80000000u) ? (ue & 0x7fffffffu) : ~ue;
        const float thr = __uint_as_float(uv) - 1e-2f;
        const float* row = out + ((size_t)b * SS + t + 1) * VV;
        unsigned long long best = 0ull;
        for (int n4 = qtr * 2000 + tid; n4 < (qtr + 1) * 2000; n4 += 512) {
            float4 v = __ldcg((const float4*)&row[n4 * 4]);
            float mv = fmaxf(fmaxf(v.x, v.y), fmaxf(v.z, v.w));
            if (mv >= thr) {
                float vv[4] = {v.x, v.y, v.z, v.w};
                #pragma unroll
                for (int j = 0; j < 4; j++) {
                    if (vv[j] >= thr) {
                        int n = n4 * 4 + j;
                        const float* wr = Wout + (size_t)n * HH;
                        float d = 0.f;
                        for (int k = 0; k < HH; k++) d += ax[k] * wr[k];
                        unsigned long long key = amax_key(d + bout[n], n);
                        if (key > best) best = key;
                    }
                }
            }
        }
        #pragma unroll
        for (int off = 16; off; off >>= 1) {
            unsigned long long o = __shfl_xor_sync(0xffffffffu, best, off);
            if (o > best) best = o;
        }
        __syncthreads();
        if (lane == 0 && best) atomicMax(&g_packed[b], best);
        __syncthreads();
    }
}

__global__ void __launch_bounds__(512, 1)
decoder_persist(const float* __restrict__ b_ih, const float* __restrict__ b_hh,
                const float* __restrict__ Wq, const float* __restrict__ bq,
                const float* __restrict__ Wo, const float* __restrict__ bo,
                const float* __restrict__ W_out, const float* __restrict__ b_out,
                float* __restrict__ out) {
    extern __shared__ char smem[];
    unsigned ep = 0;
    for (int t = 0; t < NSTEP; t++) {
        const int pin = t & 1, pout = pin ^ 1;
        lstm_phase(0, pin, t == 0, smem, b_ih, b_hh);
        gridbar(++ep);
        lstm_phase(1, pin, 0, smem, b_ih, b_hh);
        gridbar(++ep);
        gemm512_phase(smem, &g_h[pout][1][0][0], Wq, bq, &g_q[0][0], 0);
        gridbar(++ep);
        attn_phase(smem);
        gridbar(++ep);
        gemm512_phase(smem, &g_attnT[0][0], Wo, bo, &g_attno[0][0], 1);
        gridbar(++ep);
        logits_phase(smem, b_out, out, t);
        if (t < NSTEP - 1) {
            gridbar(++ep);
            fix_phase(smem, W_out, b_out, out, t);
            gridbar(++ep);
        }
    }
}

extern "C" void kernel_launch(void* const* d_in, const int* in_sizes, int n_in,
                              void* d_out, int out_size) {
    const float* hs     = (const float*)d_in[0];
    const float* hidden = (const float*)d_in[1];
    const float* cell   = (const float*)d_in[2];
    const float* emb    = (const float*)d_in[3];
    const float* W_ih   = (const float*)d_in[4];
    const float* W_hh   = (const float*)d_in[5];
    const float* b_ih   = (const float*)d_in[6];
    const float* b_hh   = (const float*)d_in[7];
    const float* Wq     = (const float*)d_in[8];
    const float* bq     = (const float*)d_in[9];
    const float* Wk     = (const float*)d_in[10];
    const float* bk     = (const float*)d_in[11];
    const float* Wv     = (const float*)d_in[12];
    const float* bv     = (const float*)d_in[13];
    const float* Wo     = (const float*)d_in[14];
    const float* bo     = (const float*)d_in[15];
    const float* W_out  = (const float*)d_in[16];
    const float* b_out  = (const float*)d_in[17];
    float* out = (float*)d_out;

    cudaFuncSetAttribute(decoder_persist, cudaFuncAttributeMaxDynamicSharedMemorySize, SMEM_DYN);

    init_kernel<<<4000, 256>>>(hidden, cell, W_out, emb, W_ih, W_hh, out);

    dim3 kvg(128, 4);
    kv_kernel<<<kvg, 256>>>(hs, Wk, bk, 0);
    kv_kernel<<<kvg, 256>>>(hs, Wv, bv, 1);

    decoder_persist<<<NCTA, 512, SMEM_DYN>>>(b_ih, b_hh, Wq, bq, Wo, bo, W_out, b_out, out);
}